// round 12
// baseline (speedup 1.0000x reference)
#include <cuda_runtime.h>
#include <math.h>

#define BB   512   // batch
#define TT   512   // encoder time
#define EE   512   // dim_enc
#define AA   128   // dim_att
#define RR   256   // dim_rnn
#define MELD 80
#define RFRD 2
#define INDIM 160  // RFR*MEL

// Scratch (no cudaMalloc allowed)
__device__ float g_q[BB * EE];
__device__ float g_xc[BB * RR];
__device__ float g_xc2[BB * RR];

__device__ __forceinline__ float sigf(float x) { return 1.f / (1.f + __expf(-x)); }

// ---------------------------------------------------------------------------
// Kernel 1: PreNet (2x Linear+ReLU) + attention GRUCell + q = h_new @ att_W.
// 8 batch rows / block, 128 threads. Writes h_att_new to output region,
// g_xc[:, 0:128], and g_q.
// ---------------------------------------------------------------------------
__global__ void k_prenet_gru(const float* __restrict__ x, const float* __restrict__ h_att,
                             const float* __restrict__ w1, const float* __restrict__ b1,
                             const float* __restrict__ w2, const float* __restrict__ b2,
                             const float* __restrict__ wih, const float* __restrict__ whh,
                             const float* __restrict__ bih, const float* __restrict__ bhh,
                             const float* __restrict__ attW,
                             float* __restrict__ hatt_out) {
    __shared__ float xs[8][INDIM];
    __shared__ float hs[8][AA];
    __shared__ float p1s[8][AA];
    __shared__ float p2s[8][AA];
    int b0 = blockIdx.x * 8, tid = threadIdx.x;

    for (int i = tid; i < 8 * INDIM; i += 128)
        xs[i / INDIM][i % INDIM] = x[(b0 + i / INDIM) * INDIM + i % INDIM];
    for (int i = tid; i < 8 * AA; i += 128)
        hs[i >> 7][i & 127] = h_att[(b0 + (i >> 7)) * AA + (i & 127)];
    __syncthreads();

    int j = tid;
    float acc[8];
    #pragma unroll
    for (int b = 0; b < 8; b++) acc[b] = b1[j];
    #pragma unroll 4
    for (int k = 0; k < INDIM; k++) {
        float wv = w1[j * INDIM + k];
        #pragma unroll
        for (int b = 0; b < 8; b++) acc[b] = fmaf(wv, xs[b][k], acc[b]);
    }
    #pragma unroll
    for (int b = 0; b < 8; b++) p1s[b][j] = fmaxf(acc[b], 0.f);
    __syncthreads();

    #pragma unroll
    for (int b = 0; b < 8; b++) acc[b] = b2[j];
    #pragma unroll 4
    for (int k = 0; k < AA; k++) {
        float wv = w2[j * AA + k];
        #pragma unroll
        for (int b = 0; b < 8; b++) acc[b] = fmaf(wv, p1s[b][k], acc[b]);
    }
    #pragma unroll
    for (int b = 0; b < 8; b++) p2s[b][j] = fmaxf(acc[b], 0.f);
    __syncthreads();

    float air[8], aiz[8], ain[8], ahr[8], ahz[8], ahn[8];
    float bir = bih[j], biz = bih[AA + j], binn = bih[2 * AA + j];
    float bhr = bhh[j], bhz = bhh[AA + j], bhnn = bhh[2 * AA + j];
    #pragma unroll
    for (int b = 0; b < 8; b++) {
        air[b] = bir; aiz[b] = biz; ain[b] = binn;
        ahr[b] = bhr; ahz[b] = bhz; ahn[b] = bhnn;
    }
    #pragma unroll 2
    for (int k = 0; k < AA; k++) {
        float wir = wih[j * AA + k], wiz = wih[(AA + j) * AA + k], win = wih[(2 * AA + j) * AA + k];
        float whr = whh[j * AA + k], whz = whh[(AA + j) * AA + k], whn = whh[(2 * AA + j) * AA + k];
        #pragma unroll
        for (int b = 0; b < 8; b++) {
            float pv = p2s[b][k], hv = hs[b][k];
            air[b] = fmaf(wir, pv, air[b]);
            aiz[b] = fmaf(wiz, pv, aiz[b]);
            ain[b] = fmaf(win, pv, ain[b]);
            ahr[b] = fmaf(whr, hv, ahr[b]);
            ahz[b] = fmaf(whz, hv, ahz[b]);
            ahn[b] = fmaf(whn, hv, ahn[b]);
        }
    }
    __syncthreads();   // p1s about to be reused for h_new
    #pragma unroll
    for (int b = 0; b < 8; b++) {
        float r = sigf(air[b] + ahr[b]);
        float z = sigf(aiz[b] + ahz[b]);
        float n = tanhf(ain[b] + r * ahn[b]);
        float hn = (1.f - z) * n + z * hs[b][j];
        hatt_out[(b0 + b) * AA + j] = hn;
        g_xc[(b0 + b) * RR + j] = hn;
        p1s[b][j] = hn;                 // stage for the q GEMM
    }
    __syncthreads();

    // q = h_new @ att_W   (att_W: [A, E] row-major, q = h @ W)
    float q0[8], q1[8], q2[8], q3[8];
    #pragma unroll
    for (int b = 0; b < 8; b++) { q0[b] = 0.f; q1[b] = 0.f; q2[b] = 0.f; q3[b] = 0.f; }
    #pragma unroll 2
    for (int k = 0; k < AA; k++) {
        float wv0 = attW[k * EE + tid];
        float wv1 = attW[k * EE + tid + 128];
        float wv2 = attW[k * EE + tid + 256];
        float wv3 = attW[k * EE + tid + 384];
        #pragma unroll
        for (int b = 0; b < 8; b++) {
            float hv = p1s[b][k];
            q0[b] = fmaf(wv0, hv, q0[b]);
            q1[b] = fmaf(wv1, hv, q1[b]);
            q2[b] = fmaf(wv2, hv, q2[b]);
            q3[b] = fmaf(wv3, hv, q3[b]);
        }
    }
    #pragma unroll
    for (int b = 0; b < 8; b++) {
        g_q[(b0 + b) * EE + tid]       = q0[b];
        g_q[(b0 + b) * EE + tid + 128] = q1[b];
        g_q[(b0 + b) * EE + tid + 256] = q2[b];
        g_q[(b0 + b) * EE + tid + 384] = q3[b];
    }
}

// ---------------------------------------------------------------------------
// Kernel 2: fused attention + context projection.
// One block (512 threads, 16 warps) per batch row. Warp-per-encoder-row
// streaming: each warp processes 32 rows with register-resident online-softmax
// context accumulators; encoder data never touches SMEM. Cross-warp merge via
// SMEM atomics, then ctx @ ctx_W epilogue (ctxW is L2-resident).
// ---------------------------------------------------------------------------
__global__ __launch_bounds__(512) void k_attn_fused(const float* __restrict__ enc,
                                                    const float* __restrict__ ctxW,
                                                    float* __restrict__ w_out) {
    __shared__ float sc[TT];         // raw scores
    __shared__ float ctx_s[EE];      // merged (unnormalized) context
    __shared__ float wm[16], wl[16];
    __shared__ float part[4][AA];
    int b = blockIdx.x, tid = threadIdx.x, lane = tid & 31, warp = tid >> 5;

    ctx_s[tid] = 0.f;

    // q: per-lane float4 chunks, e = chunk*128 + lane*4 + j (replicated per warp)
    const float4* q4p = (const float4*)(g_q + (size_t)b * EE);
    float4 q0 = q4p[lane], q1 = q4p[lane + 32], q2 = q4p[lane + 64], q3 = q4p[lane + 96];
    __syncthreads();

    const float4* rp = (const float4*)(enc + (size_t)b * TT * EE);
    const int t0 = warp * 32;

    float m = -INFINITY, l = 0.f;
    float4 a0 = {0,0,0,0}, a1 = {0,0,0,0}, a2 = {0,0,0,0}, a3 = {0,0,0,0};

    // prefetch row t0
    const float4* r = rp + (size_t)t0 * (EE / 4) + lane;
    float4 v0 = r[0], v1 = r[32], v2 = r[64], v3 = r[96];

    for (int i = 0; i < 32; i++) {
        float4 u0 = v0, u1 = v1, u2 = v2, u3 = v3;
        if (i < 31) {
            const float4* rn = rp + (size_t)(t0 + i + 1) * (EE / 4) + lane;
            v0 = rn[0]; v1 = rn[32]; v2 = rn[64]; v3 = rn[96];
        }
        // dot(q, row)
        float d = u0.x * q0.x;
        d = fmaf(u0.y, q0.y, d); d = fmaf(u0.z, q0.z, d); d = fmaf(u0.w, q0.w, d);
        d = fmaf(u1.x, q1.x, d); d = fmaf(u1.y, q1.y, d); d = fmaf(u1.z, q1.z, d); d = fmaf(u1.w, q1.w, d);
        d = fmaf(u2.x, q2.x, d); d = fmaf(u2.y, q2.y, d); d = fmaf(u2.z, q2.z, d); d = fmaf(u2.w, q2.w, d);
        d = fmaf(u3.x, q3.x, d); d = fmaf(u3.y, q3.y, d); d = fmaf(u3.z, q3.z, d); d = fmaf(u3.w, q3.w, d);
        #pragma unroll
        for (int o = 16; o; o >>= 1) d += __shfl_xor_sync(0xffffffffu, d, o);
        float s = d;                       // warp-uniform
        if (lane == 0) sc[t0 + i] = s;

        float mn = fmaxf(m, s);
        float p  = __expf(s - mn);
        if (s > m) {                       // warp-uniform branch: rescale needed
            float c = __expf(m - mn);      // m == -inf on first iter -> c = 0
            l *= c;
            a0.x *= c; a0.y *= c; a0.z *= c; a0.w *= c;
            a1.x *= c; a1.y *= c; a1.z *= c; a1.w *= c;
            a2.x *= c; a2.y *= c; a2.z *= c; a2.w *= c;
            a3.x *= c; a3.y *= c; a3.z *= c; a3.w *= c;
        }
        l += p;
        a0.x = fmaf(p, u0.x, a0.x); a0.y = fmaf(p, u0.y, a0.y);
        a0.z = fmaf(p, u0.z, a0.z); a0.w = fmaf(p, u0.w, a0.w);
        a1.x = fmaf(p, u1.x, a1.x); a1.y = fmaf(p, u1.y, a1.y);
        a1.z = fmaf(p, u1.z, a1.z); a1.w = fmaf(p, u1.w, a1.w);
        a2.x = fmaf(p, u2.x, a2.x); a2.y = fmaf(p, u2.y, a2.y);
        a2.z = fmaf(p, u2.z, a2.z); a2.w = fmaf(p, u2.w, a2.w);
        a3.x = fmaf(p, u3.x, a3.x); a3.y = fmaf(p, u3.y, a3.y);
        a3.z = fmaf(p, u3.z, a3.z); a3.w = fmaf(p, u3.w, a3.w);
        m = mn;
    }

    if (lane == 0) { wm[warp] = m; wl[warp] = l; }
    __syncthreads();

    // every thread computes the global (m, l) -- 16 values, cheap
    float gm = wm[0];
    #pragma unroll
    for (int w = 1; w < 16; w++) gm = fmaxf(gm, wm[w]);
    float gl = 0.f;
    #pragma unroll
    for (int w = 0; w < 16; w++) gl += wl[w] * __expf(wm[w] - gm);

    // merge this warp's context into ctx_s (scaled to the global max)
    float f = __expf(m - gm);
    int e0 = lane * 4;
    atomicAdd(&ctx_s[e0 + 0],       a0.x * f); atomicAdd(&ctx_s[e0 + 1],       a0.y * f);
    atomicAdd(&ctx_s[e0 + 2],       a0.z * f); atomicAdd(&ctx_s[e0 + 3],       a0.w * f);
    atomicAdd(&ctx_s[e0 + 128],     a1.x * f); atomicAdd(&ctx_s[e0 + 129],     a1.y * f);
    atomicAdd(&ctx_s[e0 + 130],     a1.z * f); atomicAdd(&ctx_s[e0 + 131],     a1.w * f);
    atomicAdd(&ctx_s[e0 + 256],     a2.x * f); atomicAdd(&ctx_s[e0 + 257],     a2.y * f);
    atomicAdd(&ctx_s[e0 + 258],     a2.z * f); atomicAdd(&ctx_s[e0 + 259],     a2.w * f);
    atomicAdd(&ctx_s[e0 + 384],     a3.x * f); atomicAdd(&ctx_s[e0 + 385],     a3.y * f);
    atomicAdd(&ctx_s[e0 + 386],     a3.z * f); atomicAdd(&ctx_s[e0 + 387],     a3.w * f);
    __syncthreads();

    float invl = 1.f / gl;

    // softmax weights out (TT == 512 == blockDim)
    w_out[(size_t)b * TT + tid] = __expf(sc[tid] - gm) * invl;

    // context projection: att = (ctx/l) @ ctx_W  (ctx_W: [E, A] row-major)
    int jj = tid & 127, chunk = tid >> 7;
    float a = 0.f;
    #pragma unroll 8
    for (int e = chunk * 128; e < chunk * 128 + 128; e++)
        a = fmaf(ctx_s[e], ctxW[e * AA + jj], a);
    part[chunk][jj] = a;
    __syncthreads();
    if (tid < 128)
        g_xc[(size_t)b * RR + 128 + tid] =
            (part[0][tid] + part[1][tid] + part[2][tid] + part[3][tid]) * invl;
}

// ---------------------------------------------------------------------------
// Kernel 3: residual GRUCell(256). grid (B/8, 2). Reads xc_in, writes xc_out
// (ping-pong buffers -> no cross-block read/write race).
// ---------------------------------------------------------------------------
__global__ void k_dec(const float* __restrict__ xc_in, float* __restrict__ xc_out,
                      const float* __restrict__ hdec_in,
                      const float* __restrict__ wih_all, const float* __restrict__ whh_all,
                      const float* __restrict__ bih_all, const float* __restrict__ bhh_all,
                      float* __restrict__ hdec_out, int layer) {
    __shared__ float xcs[8][RR];
    __shared__ float hs[8][RR];
    int b0 = blockIdx.x * 8, tid = threadIdx.x;
    int j = blockIdx.y * 128 + tid;
    const float* wih = wih_all + (size_t)layer * 3 * RR * RR;
    const float* whh = whh_all + (size_t)layer * 3 * RR * RR;
    const float* bih = bih_all + layer * 3 * RR;
    const float* bhh = bhh_all + layer * 3 * RR;
    const float* hin = hdec_in + (size_t)layer * BB * RR;

    for (int i = tid; i < 8 * RR; i += 128) {
        int b = i >> 8, kk = i & 255;
        xcs[b][kk] = xc_in[(b0 + b) * RR + kk];
        hs[b][kk] = hin[(b0 + b) * RR + kk];
    }
    __syncthreads();

    float air[8], aiz[8], ain[8], ahr[8], ahz[8], ahn[8];
    float bir = bih[j], biz = bih[RR + j], binn = bih[2 * RR + j];
    float bhr = bhh[j], bhz = bhh[RR + j], bhnn = bhh[2 * RR + j];
    #pragma unroll
    for (int b = 0; b < 8; b++) {
        air[b] = bir; aiz[b] = biz; ain[b] = binn;
        ahr[b] = bhr; ahz[b] = bhz; ahn[b] = bhnn;
    }
    #pragma unroll 2
    for (int k = 0; k < RR; k++) {
        float wir = wih[j * RR + k], wiz = wih[(RR + j) * RR + k], win = wih[(2 * RR + j) * RR + k];
        float whr = whh[j * RR + k], whz = whh[(RR + j) * RR + k], whn = whh[(2 * RR + j) * RR + k];
        #pragma unroll
        for (int b = 0; b < 8; b++) {
            float pv = xcs[b][k], hv = hs[b][k];
            air[b] = fmaf(wir, pv, air[b]);
            aiz[b] = fmaf(wiz, pv, aiz[b]);
            ain[b] = fmaf(win, pv, ain[b]);
            ahr[b] = fmaf(whr, hv, ahr[b]);
            ahz[b] = fmaf(whz, hv, ahz[b]);
            ahn[b] = fmaf(whn, hv, ahn[b]);
        }
    }
    #pragma unroll
    for (int b = 0; b < 8; b++) {
        float r = sigf(air[b] + ahr[b]);
        float z = sigf(aiz[b] + ahz[b]);
        float n = tanhf(ain[b] + r * ahn[b]);
        float hn = (1.f - z) * n + z * hs[b][j];
        hdec_out[(b0 + b) * RR + j] = hn;
        xc_out[(b0 + b) * RR + j] = xcs[b][j] + hn;   // residual
    }
}

// ---------------------------------------------------------------------------
// Kernel 4: out = xc @ fc_w^T + fc_b  (512x256 @ 256x160)
// ---------------------------------------------------------------------------
__global__ void k_fc(const float* __restrict__ xc_in,
                     const float* __restrict__ fcw, const float* __restrict__ fcb,
                     float* __restrict__ out) {
    __shared__ float xcs[8][RR];
    int b0 = blockIdx.x * 8, tid = threadIdx.x;
    for (int i = tid; i < 8 * RR; i += 160) {
        int b = i >> 8, kk = i & 255;
        xcs[b][kk] = xc_in[(b0 + b) * RR + kk];
    }
    __syncthreads();
    float acc[8];
    float bb = fcb[tid];
    #pragma unroll
    for (int b = 0; b < 8; b++) acc[b] = bb;
    #pragma unroll 4
    for (int k = 0; k < RR; k++) {
        float wv = fcw[tid * RR + k];
        #pragma unroll
        for (int b = 0; b < 8; b++) acc[b] = fmaf(wv, xcs[b][k], acc[b]);
    }
    #pragma unroll
    for (int b = 0; b < 8; b++)
        out[(b0 + b) * INDIM + tid] = acc[b];
}

// ---------------------------------------------------------------------------
extern "C" void kernel_launch(void* const* d_in, const int* in_sizes, int n_in,
                              void* d_out, int out_size) {
    const float* x      = (const float*)d_in[0];
    // d_in[1] = w (previous attention weights) is unused by the reference math
    const float* h_att  = (const float*)d_in[2];
    const float* h_dec  = (const float*)d_in[3];
    const float* enc    = (const float*)d_in[4];
    const float* pre_w1 = (const float*)d_in[5];
    const float* pre_b1 = (const float*)d_in[6];
    const float* pre_w2 = (const float*)d_in[7];
    const float* pre_b2 = (const float*)d_in[8];
    const float* awih   = (const float*)d_in[9];
    const float* awhh   = (const float*)d_in[10];
    const float* abih   = (const float*)d_in[11];
    const float* abhh   = (const float*)d_in[12];
    const float* attW   = (const float*)d_in[13];
    const float* ctxW   = (const float*)d_in[14];
    const float* dwih   = (const float*)d_in[15];
    const float* dwhh   = (const float*)d_in[16];
    const float* dbih   = (const float*)d_in[17];
    const float* dbhh   = (const float*)d_in[18];
    const float* fcw    = (const float*)d_in[19];
    const float* fcb    = (const float*)d_in[20];

    float* out    = (float*)d_out;
    float* w_new  = out + BB * RFRD * MELD;      // +81920
    float* hatt_o = w_new + BB * TT;             // +262144
    float* hdec_o = hatt_o + BB * AA;            // +65536

    float* xc  = nullptr;  cudaGetSymbolAddress((void**)&xc,  g_xc);
    float* xc2 = nullptr;  cudaGetSymbolAddress((void**)&xc2, g_xc2);

    k_prenet_gru<<<BB / 8, 128>>>(x, h_att, pre_w1, pre_b1, pre_w2, pre_b2,
                                  awih, awhh, abih, abhh, attW, hatt_o);
    k_attn_fused<<<BB, 512>>>(enc, ctxW, w_new);
    k_dec<<<dim3(BB / 8, 2), 128>>>(xc, xc2, h_dec, dwih, dwhh, dbih, dbhh, hdec_o, 0);
    k_dec<<<dim3(BB / 8, 2), 128>>>(xc2, xc, h_dec, dwih, dwhh, dbih, dbhh,
                                    hdec_o + BB * RR, 1);
    k_fc<<<BB / 8, 160>>>(xc, fcw, fcb, out);
}

// round 13
// speedup vs baseline: 1.5716x; 1.5716x over previous
#include <cuda_runtime.h>
#include <math.h>

#define BB   512   // batch
#define TT   512   // encoder time
#define EE   512   // dim_enc
#define AA   128   // dim_att
#define RR   256   // dim_rnn
#define MELD 80
#define RFRD 2
#define INDIM 160  // RFR*MEL

// Scratch (no cudaMalloc allowed)
__device__ float g_q[BB * EE];
__device__ float g_xc[BB * RR];
__device__ float g_xc2[BB * RR];
// Transposed weights (k-major) for coalesced access
__device__ float g_w1T[INDIM * AA];        // [160][128]
__device__ float g_w2T[AA * AA];           // [128][128]
__device__ float g_awihT[AA * 3 * AA];     // [128][384]
__device__ float g_awhhT[AA * 3 * AA];     // [128][384]
__device__ float g_dwihT[2 * RR * 3 * RR]; // [2][256][768]
__device__ float g_dwhhT[2 * RR * 3 * RR]; // [2][256][768]
__device__ float g_fcwT[RR * INDIM];       // [256][160]

__device__ __forceinline__ float sigf(float x) { return 1.f / (1.f + __expf(-x)); }

// ---------------------------------------------------------------------------
// Kernel 0: batched 32x32-tile transpose of all row-major weight matrices
// into k-major scratch. All dims are multiples of 32 -> no bounds checks.
// Tile counts: 20,16,48,48,192,192,192,192,40 => 940 blocks total.
// ---------------------------------------------------------------------------
__global__ void k_transpose_all(const float* __restrict__ w1, const float* __restrict__ w2,
                                const float* __restrict__ awih, const float* __restrict__ awhh,
                                const float* __restrict__ dwih, const float* __restrict__ dwhh,
                                const float* __restrict__ fcw) {
    __shared__ float s[32][33];
    int t = blockIdx.x;
    const float* src; float* dst; int rows, cols;
    if (t < 20)       {          src = w1;              dst = g_w1T;              rows = 128; cols = 160; }
    else if (t < 36)  { t -= 20; src = w2;              dst = g_w2T;              rows = 128; cols = 128; }
    else if (t < 84)  { t -= 36; src = awih;            dst = g_awihT;            rows = 384; cols = 128; }
    else if (t < 132) { t -= 84; src = awhh;            dst = g_awhhT;            rows = 384; cols = 128; }
    else if (t < 324) { t -= 132; src = dwih;           dst = g_dwihT;            rows = 768; cols = 256; }
    else if (t < 516) { t -= 324; src = dwhh;           dst = g_dwhhT;            rows = 768; cols = 256; }
    else if (t < 708) { t -= 516; src = dwih + 768*256; dst = g_dwihT + 256*768;  rows = 768; cols = 256; }
    else if (t < 900) { t -= 708; src = dwhh + 768*256; dst = g_dwhhT + 256*768;  rows = 768; cols = 256; }
    else              { t -= 900; src = fcw;            dst = g_fcwT;             rows = 160; cols = 256; }
    int tiles_c = cols >> 5;
    int tr = (t / tiles_c) << 5, tc = (t % tiles_c) << 5;
    int tx = threadIdx.x, ty = threadIdx.y;
    #pragma unroll
    for (int yy = 0; yy < 32; yy += 8)
        s[ty + yy][tx] = src[(size_t)(tr + ty + yy) * cols + tc + tx];
    __syncthreads();
    #pragma unroll
    for (int yy = 0; yy < 32; yy += 8)
        dst[(size_t)(tc + ty + yy) * rows + tr + tx] = s[tx][ty + yy];
}

// ---------------------------------------------------------------------------
// Kernel 1: PreNet (2x Linear+ReLU) + attention GRUCell + q = h_new @ att_W.
// 8 batch rows / block, 128 threads. All weight reads coalesced (k-major).
// ---------------------------------------------------------------------------
__global__ void k_prenet_gru(const float* __restrict__ x, const float* __restrict__ h_att,
                             const float* __restrict__ b1, const float* __restrict__ b2,
                             const float* __restrict__ bih, const float* __restrict__ bhh,
                             const float* __restrict__ attW,
                             float* __restrict__ hatt_out) {
    __shared__ float xs[8][INDIM];
    __shared__ float hs[8][AA];
    __shared__ float p1s[8][AA];
    __shared__ float p2s[8][AA];
    int b0 = blockIdx.x * 8, tid = threadIdx.x;

    for (int i = tid; i < 8 * INDIM; i += 128)
        xs[i / INDIM][i % INDIM] = x[(b0 + i / INDIM) * INDIM + i % INDIM];
    for (int i = tid; i < 8 * AA; i += 128)
        hs[i >> 7][i & 127] = h_att[(b0 + (i >> 7)) * AA + (i & 127)];
    __syncthreads();

    int j = tid;
    float acc[8];
    #pragma unroll
    for (int b = 0; b < 8; b++) acc[b] = b1[j];
    #pragma unroll 4
    for (int k = 0; k < INDIM; k++) {
        float wv = g_w1T[k * AA + j];
        #pragma unroll
        for (int b = 0; b < 8; b++) acc[b] = fmaf(wv, xs[b][k], acc[b]);
    }
    #pragma unroll
    for (int b = 0; b < 8; b++) p1s[b][j] = fmaxf(acc[b], 0.f);
    __syncthreads();

    #pragma unroll
    for (int b = 0; b < 8; b++) acc[b] = b2[j];
    #pragma unroll 4
    for (int k = 0; k < AA; k++) {
        float wv = g_w2T[k * AA + j];
        #pragma unroll
        for (int b = 0; b < 8; b++) acc[b] = fmaf(wv, p1s[b][k], acc[b]);
    }
    #pragma unroll
    for (int b = 0; b < 8; b++) p2s[b][j] = fmaxf(acc[b], 0.f);
    __syncthreads();

    float air[8], aiz[8], ain[8], ahr[8], ahz[8], ahn[8];
    float bir = bih[j], biz = bih[AA + j], binn = bih[2 * AA + j];
    float bhr = bhh[j], bhz = bhh[AA + j], bhnn = bhh[2 * AA + j];
    #pragma unroll
    for (int b = 0; b < 8; b++) {
        air[b] = bir; aiz[b] = biz; ain[b] = binn;
        ahr[b] = bhr; ahz[b] = bhz; ahn[b] = bhnn;
    }
    #pragma unroll 4
    for (int k = 0; k < AA; k++) {
        const float* wr = g_awihT + k * (3 * AA);
        const float* ur = g_awhhT + k * (3 * AA);
        float wir = wr[j], wiz = wr[AA + j], win = wr[2 * AA + j];
        float whr = ur[j], whz = ur[AA + j], whn = ur[2 * AA + j];
        #pragma unroll
        for (int b = 0; b < 8; b++) {
            float pv = p2s[b][k], hv = hs[b][k];
            air[b] = fmaf(wir, pv, air[b]);
            aiz[b] = fmaf(wiz, pv, aiz[b]);
            ain[b] = fmaf(win, pv, ain[b]);
            ahr[b] = fmaf(whr, hv, ahr[b]);
            ahz[b] = fmaf(whz, hv, ahz[b]);
            ahn[b] = fmaf(whn, hv, ahn[b]);
        }
    }
    __syncthreads();   // p1s about to be reused for h_new
    #pragma unroll
    for (int b = 0; b < 8; b++) {
        float r = sigf(air[b] + ahr[b]);
        float z = sigf(aiz[b] + ahz[b]);
        float n = tanhf(ain[b] + r * ahn[b]);
        float hn = (1.f - z) * n + z * hs[b][j];
        hatt_out[(b0 + b) * AA + j] = hn;
        g_xc[(b0 + b) * RR + j] = hn;
        p1s[b][j] = hn;                 // stage for the q GEMM
    }
    __syncthreads();

    // q = h_new @ att_W   (att_W: [A, E] row-major; already coalesced)
    float q0[8], q1[8], q2[8], q3[8];
    #pragma unroll
    for (int b = 0; b < 8; b++) { q0[b] = 0.f; q1[b] = 0.f; q2[b] = 0.f; q3[b] = 0.f; }
    #pragma unroll 2
    for (int k = 0; k < AA; k++) {
        float wv0 = attW[k * EE + tid];
        float wv1 = attW[k * EE + tid + 128];
        float wv2 = attW[k * EE + tid + 256];
        float wv3 = attW[k * EE + tid + 384];
        #pragma unroll
        for (int b = 0; b < 8; b++) {
            float hv = p1s[b][k];
            q0[b] = fmaf(wv0, hv, q0[b]);
            q1[b] = fmaf(wv1, hv, q1[b]);
            q2[b] = fmaf(wv2, hv, q2[b]);
            q3[b] = fmaf(wv3, hv, q3[b]);
        }
    }
    #pragma unroll
    for (int b = 0; b < 8; b++) {
        g_q[(b0 + b) * EE + tid]       = q0[b];
        g_q[(b0 + b) * EE + tid + 128] = q1[b];
        g_q[(b0 + b) * EE + tid + 256] = q2[b];
        g_q[(b0 + b) * EE + tid + 384] = q3[b];
    }
}

// ---------------------------------------------------------------------------
// Kernel 2: fused attention + context projection (unchanged this round).
// ---------------------------------------------------------------------------
__global__ __launch_bounds__(512) void k_attn_fused(const float* __restrict__ enc,
                                                    const float* __restrict__ ctxW,
                                                    float* __restrict__ w_out) {
    __shared__ float sc[TT];
    __shared__ float ctx_s[EE];
    __shared__ float wm[16], wl[16];
    __shared__ float part[4][AA];
    int b = blockIdx.x, tid = threadIdx.x, lane = tid & 31, warp = tid >> 5;

    ctx_s[tid] = 0.f;

    const float4* q4p = (const float4*)(g_q + (size_t)b * EE);
    float4 q0 = q4p[lane], q1 = q4p[lane + 32], q2 = q4p[lane + 64], q3 = q4p[lane + 96];
    __syncthreads();

    const float4* rp = (const float4*)(enc + (size_t)b * TT * EE);
    const int t0 = warp * 32;

    float m = -INFINITY, l = 0.f;
    float4 a0 = {0,0,0,0}, a1 = {0,0,0,0}, a2 = {0,0,0,0}, a3 = {0,0,0,0};

    const float4* r = rp + (size_t)t0 * (EE / 4) + lane;
    float4 v0 = r[0], v1 = r[32], v2 = r[64], v3 = r[96];

    for (int i = 0; i < 32; i++) {
        float4 u0 = v0, u1 = v1, u2 = v2, u3 = v3;
        if (i < 31) {
            const float4* rn = rp + (size_t)(t0 + i + 1) * (EE / 4) + lane;
            v0 = rn[0]; v1 = rn[32]; v2 = rn[64]; v3 = rn[96];
        }
        float d = u0.x * q0.x;
        d = fmaf(u0.y, q0.y, d); d = fmaf(u0.z, q0.z, d); d = fmaf(u0.w, q0.w, d);
        d = fmaf(u1.x, q1.x, d); d = fmaf(u1.y, q1.y, d); d = fmaf(u1.z, q1.z, d); d = fmaf(u1.w, q1.w, d);
        d = fmaf(u2.x, q2.x, d); d = fmaf(u2.y, q2.y, d); d = fmaf(u2.z, q2.z, d); d = fmaf(u2.w, q2.w, d);
        d = fmaf(u3.x, q3.x, d); d = fmaf(u3.y, q3.y, d); d = fmaf(u3.z, q3.z, d); d = fmaf(u3.w, q3.w, d);
        #pragma unroll
        for (int o = 16; o; o >>= 1) d += __shfl_xor_sync(0xffffffffu, d, o);
        float s = d;
        if (lane == 0) sc[t0 + i] = s;

        float mn = fmaxf(m, s);
        float p  = __expf(s - mn);
        if (s > m) {
            float c = __expf(m - mn);
            l *= c;
            a0.x *= c; a0.y *= c; a0.z *= c; a0.w *= c;
            a1.x *= c; a1.y *= c; a1.z *= c; a1.w *= c;
            a2.x *= c; a2.y *= c; a2.z *= c; a2.w *= c;
            a3.x *= c; a3.y *= c; a3.z *= c; a3.w *= c;
        }
        l += p;
        a0.x = fmaf(p, u0.x, a0.x); a0.y = fmaf(p, u0.y, a0.y);
        a0.z = fmaf(p, u0.z, a0.z); a0.w = fmaf(p, u0.w, a0.w);
        a1.x = fmaf(p, u1.x, a1.x); a1.y = fmaf(p, u1.y, a1.y);
        a1.z = fmaf(p, u1.z, a1.z); a1.w = fmaf(p, u1.w, a1.w);
        a2.x = fmaf(p, u2.x, a2.x); a2.y = fmaf(p, u2.y, a2.y);
        a2.z = fmaf(p, u2.z, a2.z); a2.w = fmaf(p, u2.w, a2.w);
        a3.x = fmaf(p, u3.x, a3.x); a3.y = fmaf(p, u3.y, a3.y);
        a3.z = fmaf(p, u3.z, a3.z); a3.w = fmaf(p, u3.w, a3.w);
        m = mn;
    }

    if (lane == 0) { wm[warp] = m; wl[warp] = l; }
    __syncthreads();

    float gm = wm[0];
    #pragma unroll
    for (int w = 1; w < 16; w++) gm = fmaxf(gm, wm[w]);
    float gl = 0.f;
    #pragma unroll
    for (int w = 0; w < 16; w++) gl += wl[w] * __expf(wm[w] - gm);

    float f = __expf(m - gm);
    int e0 = lane * 4;
    atomicAdd(&ctx_s[e0 + 0],   a0.x * f); atomicAdd(&ctx_s[e0 + 1],   a0.y * f);
    atomicAdd(&ctx_s[e0 + 2],   a0.z * f); atomicAdd(&ctx_s[e0 + 3],   a0.w * f);
    atomicAdd(&ctx_s[e0 + 128], a1.x * f); atomicAdd(&ctx_s[e0 + 129], a1.y * f);
    atomicAdd(&ctx_s[e0 + 130], a1.z * f); atomicAdd(&ctx_s[e0 + 131], a1.w * f);
    atomicAdd(&ctx_s[e0 + 256], a2.x * f); atomicAdd(&ctx_s[e0 + 257], a2.y * f);
    atomicAdd(&ctx_s[e0 + 258], a2.z * f); atomicAdd(&ctx_s[e0 + 259], a2.w * f);
    atomicAdd(&ctx_s[e0 + 384], a3.x * f); atomicAdd(&ctx_s[e0 + 385], a3.y * f);
    atomicAdd(&ctx_s[e0 + 386], a3.z * f); atomicAdd(&ctx_s[e0 + 387], a3.w * f);
    __syncthreads();

    float invl = 1.f / gl;
    w_out[(size_t)b * TT + tid] = __expf(sc[tid] - gm) * invl;

    int jj = tid & 127, chunk = tid >> 7;
    float a = 0.f;
    #pragma unroll 8
    for (int e = chunk * 128; e < chunk * 128 + 128; e++)
        a = fmaf(ctx_s[e], ctxW[e * AA + jj], a);
    part[chunk][jj] = a;
    __syncthreads();
    if (tid < 128)
        g_xc[(size_t)b * RR + 128 + tid] =
            (part[0][tid] + part[1][tid] + part[2][tid] + part[3][tid]) * invl;
}

// ---------------------------------------------------------------------------
// Kernel 3: residual GRUCell(256), k-major (transposed) weights -> coalesced.
// grid (B/8, 2); ping-pong xc buffers.
// ---------------------------------------------------------------------------
__global__ __launch_bounds__(128) void k_dec(const float* __restrict__ xc_in, float* __restrict__ xc_out,
                      const float* __restrict__ hdec_in,
                      const float* __restrict__ bih_all, const float* __restrict__ bhh_all,
                      float* __restrict__ hdec_out, int layer) {
    __shared__ float xcs[8][RR];
    __shared__ float hs[8][RR];
    int b0 = blockIdx.x * 8, tid = threadIdx.x;
    int j = blockIdx.y * 128 + tid;
    const float* wT = g_dwihT + (size_t)layer * RR * 3 * RR;
    const float* uT = g_dwhhT + (size_t)layer * RR * 3 * RR;
    const float* bih = bih_all + layer * 3 * RR;
    const float* bhh = bhh_all + layer * 3 * RR;
    const float* hin = hdec_in + (size_t)layer * BB * RR;

    for (int i = tid; i < 8 * RR; i += 128) {
        int b = i >> 8, kk = i & 255;
        xcs[b][kk] = xc_in[(b0 + b) * RR + kk];
        hs[b][kk] = hin[(b0 + b) * RR + kk];
    }
    __syncthreads();

    float air[8], aiz[8], ain[8], ahr[8], ahz[8], ahn[8];
    float bir = bih[j], biz = bih[RR + j], binn = bih[2 * RR + j];
    float bhr = bhh[j], bhz = bhh[RR + j], bhnn = bhh[2 * RR + j];
    #pragma unroll
    for (int b = 0; b < 8; b++) {
        air[b] = bir; aiz[b] = biz; ain[b] = binn;
        ahr[b] = bhr; ahz[b] = bhz; ahn[b] = bhnn;
    }
    #pragma unroll 4
    for (int k = 0; k < RR; k++) {
        const float* wr = wT + (size_t)k * (3 * RR);
        const float* ur = uT + (size_t)k * (3 * RR);
        float wir = wr[j], wiz = wr[RR + j], win = wr[2 * RR + j];
        float whr = ur[j], whz = ur[RR + j], whn = ur[2 * RR + j];
        #pragma unroll
        for (int b = 0; b < 8; b++) {
            float pv = xcs[b][k], hv = hs[b][k];
            air[b] = fmaf(wir, pv, air[b]);
            aiz[b] = fmaf(wiz, pv, aiz[b]);
            ain[b] = fmaf(win, pv, ain[b]);
            ahr[b] = fmaf(whr, hv, ahr[b]);
            ahz[b] = fmaf(whz, hv, ahz[b]);
            ahn[b] = fmaf(whn, hv, ahn[b]);
        }
    }
    #pragma unroll
    for (int b = 0; b < 8; b++) {
        float r = sigf(air[b] + ahr[b]);
        float z = sigf(aiz[b] + ahz[b]);
        float n = tanhf(ain[b] + r * ahn[b]);
        float hn = (1.f - z) * n + z * hs[b][j];
        hdec_out[(b0 + b) * RR + j] = hn;
        xc_out[(b0 + b) * RR + j] = xcs[b][j] + hn;   // residual
    }
}

// ---------------------------------------------------------------------------
// Kernel 4: out = xc @ fc_w^T + fc_b, k-major fc weights -> coalesced.
// ---------------------------------------------------------------------------
__global__ void k_fc(const float* __restrict__ xc_in,
                     const float* __restrict__ fcb,
                     float* __restrict__ out) {
    __shared__ float xcs[8][RR];
    int b0 = blockIdx.x * 8, tid = threadIdx.x;
    for (int i = tid; i < 8 * RR; i += 160) {
        int b = i >> 8, kk = i & 255;
        xcs[b][kk] = xc_in[(b0 + b) * RR + kk];
    }
    __syncthreads();
    float acc[8];
    float bb = fcb[tid];
    #pragma unroll
    for (int b = 0; b < 8; b++) acc[b] = bb;
    #pragma unroll 4
    for (int k = 0; k < RR; k++) {
        float wv = g_fcwT[k * INDIM + tid];
        #pragma unroll
        for (int b = 0; b < 8; b++) acc[b] = fmaf(wv, xcs[b][k], acc[b]);
    }
    #pragma unroll
    for (int b = 0; b < 8; b++)
        out[(b0 + b) * INDIM + tid] = acc[b];
}

// ---------------------------------------------------------------------------
extern "C" void kernel_launch(void* const* d_in, const int* in_sizes, int n_in,
                              void* d_out, int out_size) {
    const float* x      = (const float*)d_in[0];
    // d_in[1] = w (previous attention weights) is unused by the reference math
    const float* h_att  = (const float*)d_in[2];
    const float* h_dec  = (const float*)d_in[3];
    const float* enc    = (const float*)d_in[4];
    const float* pre_w1 = (const float*)d_in[5];
    const float* pre_b1 = (const float*)d_in[6];
    const float* pre_w2 = (const float*)d_in[7];
    const float* pre_b2 = (const float*)d_in[8];
    const float* awih   = (const float*)d_in[9];
    const float* awhh   = (const float*)d_in[10];
    const float* abih   = (const float*)d_in[11];
    const float* abhh   = (const float*)d_in[12];
    const float* attW   = (const float*)d_in[13];
    const float* ctxW   = (const float*)d_in[14];
    const float* dwih   = (const float*)d_in[15];
    const float* dwhh   = (const float*)d_in[16];
    const float* dbih   = (const float*)d_in[17];
    const float* dbhh   = (const float*)d_in[18];
    const float* fcw    = (const float*)d_in[19];
    const float* fcb    = (const float*)d_in[20];

    float* out    = (float*)d_out;
    float* w_new  = out + BB * RFRD * MELD;      // +81920
    float* hatt_o = w_new + BB * TT;             // +262144
    float* hdec_o = hatt_o + BB * AA;            // +65536

    float* xc  = nullptr;  cudaGetSymbolAddress((void**)&xc,  g_xc);
    float* xc2 = nullptr;  cudaGetSymbolAddress((void**)&xc2, g_xc2);

    k_transpose_all<<<940, dim3(32, 8)>>>(pre_w1, pre_w2, awih, awhh, dwih, dwhh, fcw);
    k_prenet_gru<<<BB / 8, 128>>>(x, h_att, pre_b1, pre_b2, abih, abhh, attW, hatt_o);
    k_attn_fused<<<BB, 512>>>(enc, ctxW, w_new);
    k_dec<<<dim3(BB / 8, 2), 128>>>(xc, xc2, h_dec, dbih, dbhh, hdec_o, 0);
    k_dec<<<dim3(BB / 8, 2), 128>>>(xc2, xc, h_dec, dbih, dbhh, hdec_o + BB * RR, 1);
    k_fc<<<BB / 8, 160>>>(xc, fcb, out);
}

// round 14
// speedup vs baseline: 1.6675x; 1.0610x over previous
#include <cuda_runtime.h>
#include <math.h>

#define BB   512   // batch
#define TT   512   // encoder time
#define EE   512   // dim_enc
#define AA   128   // dim_att
#define RR   256   // dim_rnn
#define MELD 80
#define RFRD 2
#define INDIM 160  // RFR*MEL

// Scratch (no cudaMalloc allowed)
__device__ float g_q[BB * EE];
__device__ float g_xc[BB * RR];
__device__ float g_xc2[BB * RR];
__device__ float g_g[BB * 6 * RR];         // GRU pre-activations [512][1536]
// Transposed weights (k-major) for coalesced access
__device__ float g_w1T[INDIM * AA];        // [160][128]
__device__ float g_w2T[AA * AA];           // [128][128]
__device__ float g_awihT[AA * 3 * AA];     // [128][384]
__device__ float g_awhhT[AA * 3 * AA];     // [128][384]
__device__ float g_dwihT[2 * RR * 3 * RR]; // [2][256][768]
__device__ float g_dwhhT[2 * RR * 3 * RR]; // [2][256][768]
__device__ float g_fcwT[RR * INDIM];       // [256][160]

__device__ __forceinline__ float sigf(float x) { return 1.f / (1.f + __expf(-x)); }

// ---------------------------------------------------------------------------
// Kernel 0: batched 32x32-tile transpose of all row-major weight matrices.
// ---------------------------------------------------------------------------
__global__ void k_transpose_all(const float* __restrict__ w1, const float* __restrict__ w2,
                                const float* __restrict__ awih, const float* __restrict__ awhh,
                                const float* __restrict__ dwih, const float* __restrict__ dwhh,
                                const float* __restrict__ fcw) {
    __shared__ float s[32][33];
    int t = blockIdx.x;
    const float* src; float* dst; int rows, cols;
    if (t < 20)       {          src = w1;              dst = g_w1T;              rows = 128; cols = 160; }
    else if (t < 36)  { t -= 20; src = w2;              dst = g_w2T;              rows = 128; cols = 128; }
    else if (t < 84)  { t -= 36; src = awih;            dst = g_awihT;            rows = 384; cols = 128; }
    else if (t < 132) { t -= 84; src = awhh;            dst = g_awhhT;            rows = 384; cols = 128; }
    else if (t < 324) { t -= 132; src = dwih;           dst = g_dwihT;            rows = 768; cols = 256; }
    else if (t < 516) { t -= 324; src = dwhh;           dst = g_dwhhT;            rows = 768; cols = 256; }
    else if (t < 708) { t -= 516; src = dwih + 768*256; dst = g_dwihT + 256*768;  rows = 768; cols = 256; }
    else if (t < 900) { t -= 708; src = dwhh + 768*256; dst = g_dwhhT + 256*768;  rows = 768; cols = 256; }
    else              { t -= 900; src = fcw;            dst = g_fcwT;             rows = 160; cols = 256; }
    int tiles_c = cols >> 5;
    int tr = (t / tiles_c) << 5, tc = (t % tiles_c) << 5;
    int tx = threadIdx.x, ty = threadIdx.y;
    #pragma unroll
    for (int yy = 0; yy < 32; yy += 8)
        s[ty + yy][tx] = src[(size_t)(tr + ty + yy) * cols + tc + tx];
    __syncthreads();
    #pragma unroll
    for (int yy = 0; yy < 32; yy += 8)
        dst[(size_t)(tc + ty + yy) * rows + tr + tx] = s[tx][ty + yy];
}

// ---------------------------------------------------------------------------
// Kernel 1: PreNet (2x Linear+ReLU) + attention GRUCell.
// 4 batch rows / block, 128 threads, grid 128.
// ---------------------------------------------------------------------------
__global__ __launch_bounds__(128) void k_prenet(const float* __restrict__ x, const float* __restrict__ h_att,
                         const float* __restrict__ b1, const float* __restrict__ b2,
                         const float* __restrict__ bih, const float* __restrict__ bhh,
                         float* __restrict__ hatt_out) {
    __shared__ float xs[4][INDIM];
    __shared__ float hs[4][AA];
    __shared__ float p1s[4][AA];
    __shared__ float p2s[4][AA];
    int b0 = blockIdx.x * 4, tid = threadIdx.x, j = tid;

    for (int i = tid; i < 4 * INDIM; i += 128)
        xs[i / INDIM][i % INDIM] = x[(b0 + i / INDIM) * INDIM + i % INDIM];
    for (int i = tid; i < 4 * AA; i += 128)
        hs[i >> 7][i & 127] = h_att[(b0 + (i >> 7)) * AA + (i & 127)];
    __syncthreads();

    float acc[4];
    #pragma unroll
    for (int b = 0; b < 4; b++) acc[b] = b1[j];
    #pragma unroll 8
    for (int k = 0; k < INDIM; k++) {
        float wv = g_w1T[k * AA + j];
        #pragma unroll
        for (int b = 0; b < 4; b++) acc[b] = fmaf(wv, xs[b][k], acc[b]);
    }
    #pragma unroll
    for (int b = 0; b < 4; b++) p1s[b][j] = fmaxf(acc[b], 0.f);
    __syncthreads();

    #pragma unroll
    for (int b = 0; b < 4; b++) acc[b] = b2[j];
    #pragma unroll 8
    for (int k = 0; k < AA; k++) {
        float wv = g_w2T[k * AA + j];
        #pragma unroll
        for (int b = 0; b < 4; b++) acc[b] = fmaf(wv, p1s[b][k], acc[b]);
    }
    #pragma unroll
    for (int b = 0; b < 4; b++) p2s[b][j] = fmaxf(acc[b], 0.f);
    __syncthreads();

    float air[4], aiz[4], ain[4], ahr[4], ahz[4], ahn[4];
    float bir = bih[j], biz = bih[AA + j], binn = bih[2 * AA + j];
    float bhr = bhh[j], bhz = bhh[AA + j], bhnn = bhh[2 * AA + j];
    #pragma unroll
    for (int b = 0; b < 4; b++) {
        air[b] = bir; aiz[b] = biz; ain[b] = binn;
        ahr[b] = bhr; ahz[b] = bhz; ahn[b] = bhnn;
    }
    #pragma unroll 4
    for (int k = 0; k < AA; k++) {
        const float* wr = g_awihT + k * (3 * AA);
        const float* ur = g_awhhT + k * (3 * AA);
        float wir = wr[j], wiz = wr[AA + j], win = wr[2 * AA + j];
        float whr = ur[j], whz = ur[AA + j], whn = ur[2 * AA + j];
        #pragma unroll
        for (int b = 0; b < 4; b++) {
            float pv = p2s[b][k], hv = hs[b][k];
            air[b] = fmaf(wir, pv, air[b]);
            aiz[b] = fmaf(wiz, pv, aiz[b]);
            ain[b] = fmaf(win, pv, ain[b]);
            ahr[b] = fmaf(whr, hv, ahr[b]);
            ahz[b] = fmaf(whz, hv, ahz[b]);
            ahn[b] = fmaf(whn, hv, ahn[b]);
        }
    }
    #pragma unroll
    for (int b = 0; b < 4; b++) {
        float r = sigf(air[b] + ahr[b]);
        float z = sigf(aiz[b] + ahz[b]);
        float n = tanhf(ain[b] + r * ahn[b]);
        float hn = (1.f - z) * n + z * hs[b][j];
        hatt_out[(b0 + b) * AA + j] = hn;
        g_xc[(b0 + b) * RR + j] = hn;
    }
}

// ---------------------------------------------------------------------------
// Kernel 1b: q = h_new @ att_W  (512x128 @ 128x512). grid (64,4), 8 batch rows
// and 128 q-columns per block.
// ---------------------------------------------------------------------------
__global__ __launch_bounds__(128) void k_q(const float* __restrict__ h, const float* __restrict__ attW) {
    __shared__ float hs[8][AA];
    int b0 = blockIdx.x * 8, tid = threadIdx.x;
    int col = blockIdx.y * 128 + tid;
    for (int i = tid; i < 8 * AA; i += 128)
        hs[i >> 7][i & 127] = h[(b0 + (i >> 7)) * AA + (i & 127)];
    __syncthreads();
    float acc[8];
    #pragma unroll
    for (int b = 0; b < 8; b++) acc[b] = 0.f;
    #pragma unroll 8
    for (int k = 0; k < AA; k++) {
        float wv = attW[k * EE + col];
        #pragma unroll
        for (int b = 0; b < 8; b++) acc[b] = fmaf(wv, hs[b][k], acc[b]);
    }
    #pragma unroll
    for (int b = 0; b < 8; b++)
        g_q[(b0 + b) * EE + col] = acc[b];
}

// ---------------------------------------------------------------------------
// Kernel 2: fused attention + context projection. One block (512 thr) per
// batch row; two-buffer unroll-2 streaming pipeline.
// ---------------------------------------------------------------------------
#define LOADROW(D0, D1, D2, D3, TI) do { \
    const float4* _rr = rp + (size_t)(TI) * (EE / 4) + lane; \
    D0 = _rr[0]; D1 = _rr[32]; D2 = _rr[64]; D3 = _rr[96]; } while (0)

#define PROC(U0, U1, U2, U3, TI) do { \
    float d = U0.x * q0.x; \
    d = fmaf(U0.y, q0.y, d); d = fmaf(U0.z, q0.z, d); d = fmaf(U0.w, q0.w, d); \
    d = fmaf(U1.x, q1.x, d); d = fmaf(U1.y, q1.y, d); d = fmaf(U1.z, q1.z, d); d = fmaf(U1.w, q1.w, d); \
    d = fmaf(U2.x, q2.x, d); d = fmaf(U2.y, q2.y, d); d = fmaf(U2.z, q2.z, d); d = fmaf(U2.w, q2.w, d); \
    d = fmaf(U3.x, q3.x, d); d = fmaf(U3.y, q3.y, d); d = fmaf(U3.z, q3.z, d); d = fmaf(U3.w, q3.w, d); \
    _Pragma("unroll") \
    for (int _o = 16; _o; _o >>= 1) d += __shfl_xor_sync(0xffffffffu, d, _o); \
    if (lane == 0) sc[TI] = d; \
    float mn = fmaxf(m, d); \
    float p  = __expf(d - mn); \
    if (d > m) { \
        float cc = __expf(m - mn); \
        l *= cc; \
        a0.x *= cc; a0.y *= cc; a0.z *= cc; a0.w *= cc; \
        a1.x *= cc; a1.y *= cc; a1.z *= cc; a1.w *= cc; \
        a2.x *= cc; a2.y *= cc; a2.z *= cc; a2.w *= cc; \
        a3.x *= cc; a3.y *= cc; a3.z *= cc; a3.w *= cc; \
    } \
    l += p; \
    a0.x = fmaf(p, U0.x, a0.x); a0.y = fmaf(p, U0.y, a0.y); \
    a0.z = fmaf(p, U0.z, a0.z); a0.w = fmaf(p, U0.w, a0.w); \
    a1.x = fmaf(p, U1.x, a1.x); a1.y = fmaf(p, U1.y, a1.y); \
    a1.z = fmaf(p, U1.z, a1.z); a1.w = fmaf(p, U1.w, a1.w); \
    a2.x = fmaf(p, U2.x, a2.x); a2.y = fmaf(p, U2.y, a2.y); \
    a2.z = fmaf(p, U2.z, a2.z); a2.w = fmaf(p, U2.w, a2.w); \
    a3.x = fmaf(p, U3.x, a3.x); a3.y = fmaf(p, U3.y, a3.y); \
    a3.z = fmaf(p, U3.z, a3.z); a3.w = fmaf(p, U3.w, a3.w); \
    m = mn; } while (0)

__global__ __launch_bounds__(512) void k_attn_fused(const float* __restrict__ enc,
                                                    const float* __restrict__ ctxW,
                                                    float* __restrict__ w_out) {
    __shared__ float sc[TT];
    __shared__ float ctx_s[EE];
    __shared__ float wm[16], wl[16];
    __shared__ float part[4][AA];
    int b = blockIdx.x, tid = threadIdx.x, lane = tid & 31, warp = tid >> 5;

    ctx_s[tid] = 0.f;

    const float4* q4p = (const float4*)(g_q + (size_t)b * EE);
    float4 q0 = q4p[lane], q1 = q4p[lane + 32], q2 = q4p[lane + 64], q3 = q4p[lane + 96];
    __syncthreads();

    const float4* rp = (const float4*)(enc + (size_t)b * TT * EE);
    const int t0 = warp * 32;

    float m = -INFINITY, l = 0.f;
    float4 a0 = {0,0,0,0}, a1 = {0,0,0,0}, a2 = {0,0,0,0}, a3 = {0,0,0,0};

    float4 A0, A1, A2, A3, B0, B1, B2, B3;
    LOADROW(A0, A1, A2, A3, t0);
    LOADROW(B0, B1, B2, B3, t0 + 1);

    #pragma unroll 4
    for (int i = 0; i < 32; i += 2) {
        PROC(A0, A1, A2, A3, t0 + i);
        if (i + 2 < 32) LOADROW(A0, A1, A2, A3, t0 + i + 2);
        PROC(B0, B1, B2, B3, t0 + i + 1);
        if (i + 3 < 32) LOADROW(B0, B1, B2, B3, t0 + i + 3);
    }

    if (lane == 0) { wm[warp] = m; wl[warp] = l; }
    __syncthreads();

    float gm = wm[0];
    #pragma unroll
    for (int w = 1; w < 16; w++) gm = fmaxf(gm, wm[w]);
    float gl = 0.f;
    #pragma unroll
    for (int w = 0; w < 16; w++) gl += wl[w] * __expf(wm[w] - gm);

    float f = __expf(m - gm);
    int e0 = lane * 4;
    atomicAdd(&ctx_s[e0 + 0],   a0.x * f); atomicAdd(&ctx_s[e0 + 1],   a0.y * f);
    atomicAdd(&ctx_s[e0 + 2],   a0.z * f); atomicAdd(&ctx_s[e0 + 3],   a0.w * f);
    atomicAdd(&ctx_s[e0 + 128], a1.x * f); atomicAdd(&ctx_s[e0 + 129], a1.y * f);
    atomicAdd(&ctx_s[e0 + 130], a1.z * f); atomicAdd(&ctx_s[e0 + 131], a1.w * f);
    atomicAdd(&ctx_s[e0 + 256], a2.x * f); atomicAdd(&ctx_s[e0 + 257], a2.y * f);
    atomicAdd(&ctx_s[e0 + 258], a2.z * f); atomicAdd(&ctx_s[e0 + 259], a2.w * f);
    atomicAdd(&ctx_s[e0 + 384], a3.x * f); atomicAdd(&ctx_s[e0 + 385], a3.y * f);
    atomicAdd(&ctx_s[e0 + 386], a3.z * f); atomicAdd(&ctx_s[e0 + 387], a3.w * f);
    __syncthreads();

    float invl = 1.f / gl;
    w_out[(size_t)b * TT + tid] = __expf(sc[tid] - gm) * invl;

    int jj = tid & 127, chunk = tid >> 7;
    float a = 0.f;
    #pragma unroll 8
    for (int e = chunk * 128; e < chunk * 128 + 128; e++)
        a = fmaf(ctx_s[e], ctxW[e * AA + jj], a);
    part[chunk][jj] = a;
    __syncthreads();
    if (tid < 128)
        g_xc[(size_t)b * RR + 128 + tid] =
            (part[0][tid] + part[1][tid] + part[2][tid] + part[3][tid]) * invl;
}

// ---------------------------------------------------------------------------
// Kernel 3a: GRU pre-activation GEMM, G[512][1536] = act @ W^T + bias.
// grid (64, 12): 8 batch rows x 128 of 1536 output cols. Cols [0,768) = gi
// (act = xc, W = wihT); cols [768,1536) = gh (act = h, W = whhT).
// ---------------------------------------------------------------------------
__global__ __launch_bounds__(128) void k_dec_gemm(const float* __restrict__ xc_in,
                                                  const float* __restrict__ hdec_in,
                                                  const float* __restrict__ bih_all,
                                                  const float* __restrict__ bhh_all,
                                                  int layer) {
    __shared__ float as[8][RR];
    int b0 = blockIdx.x * 8, tid = threadIdx.x, yt = blockIdx.y;
    int c = (yt % 6) * 128 + tid;           // col within [0,768)
    bool is_ih = (yt < 6);
    const float* act  = is_ih ? xc_in : (hdec_in + (size_t)layer * BB * RR);
    const float* W    = (is_ih ? g_dwihT : g_dwhhT) + (size_t)layer * RR * 3 * RR;
    const float* bias = (is_ih ? bih_all : bhh_all) + layer * 3 * RR;

    for (int i = tid; i < 8 * RR; i += 128) {
        int b = i >> 8, kk = i & 255;
        as[b][kk] = act[(b0 + b) * RR + kk];
    }
    __syncthreads();

    float acc[8];
    float bv = bias[c];
    #pragma unroll
    for (int b = 0; b < 8; b++) acc[b] = bv;

    #pragma unroll 2
    for (int k = 0; k < RR; k += 4) {
        float w0 = W[(size_t)(k + 0) * 768 + c];
        float w1 = W[(size_t)(k + 1) * 768 + c];
        float w2 = W[(size_t)(k + 2) * 768 + c];
        float w3 = W[(size_t)(k + 3) * 768 + c];
        #pragma unroll
        for (int b = 0; b < 8; b++) {
            float4 av = *(const float4*)&as[b][k];
            acc[b] = fmaf(w0, av.x, acc[b]);
            acc[b] = fmaf(w1, av.y, acc[b]);
            acc[b] = fmaf(w2, av.z, acc[b]);
            acc[b] = fmaf(w3, av.w, acc[b]);
        }
    }
    #pragma unroll
    for (int b = 0; b < 8; b++)
        g_g[(size_t)(b0 + b) * 1536 + yt * 128 + tid] = acc[b];
}

// ---------------------------------------------------------------------------
// Kernel 3b: GRU gate elementwise. grid 512, block 256.
// ---------------------------------------------------------------------------
__global__ __launch_bounds__(256) void k_dec_gates(const float* __restrict__ xc_in,
                                                   const float* __restrict__ hdec_in,
                                                   float* __restrict__ hdec_out,
                                                   float* __restrict__ xc_out, int layer) {
    int b = blockIdx.x, j = threadIdx.x;
    const float* Gb = g_g + (size_t)b * 1536;
    float gr = Gb[j],        gz = Gb[256 + j],  gn = Gb[512 + j];
    float hr = Gb[768 + j],  hz = Gb[1024 + j], hnv = Gb[1280 + j];
    float h  = hdec_in[(size_t)layer * BB * RR + b * RR + j];
    float xc = xc_in[b * RR + j];
    float r = sigf(gr + hr);
    float z = sigf(gz + hz);
    float n = tanhf(gn + r * hnv);
    float hn = (1.f - z) * n + z * h;
    hdec_out[b * RR + j] = hn;
    xc_out[b * RR + j]   = xc + hn;
}

// ---------------------------------------------------------------------------
// Kernel 4: out = xc @ fc_w^T + fc_b. 4 batch rows/block, grid 128.
// ---------------------------------------------------------------------------
__global__ __launch_bounds__(160) void k_fc(const float* __restrict__ xc_in,
                     const float* __restrict__ fcb,
                     float* __restrict__ out) {
    __shared__ float xcs[4][RR];
    int b0 = blockIdx.x * 4, tid = threadIdx.x;
    for (int i = tid; i < 4 * RR; i += 160) {
        int b = i >> 8, kk = i & 255;
        xcs[b][kk] = xc_in[(b0 + b) * RR + kk];
    }
    __syncthreads();
    float acc[4];
    float bb = fcb[tid];
    #pragma unroll
    for (int b = 0; b < 4; b++) acc[b] = bb;
    #pragma unroll 8
    for (int k = 0; k < RR; k++) {
        float wv = g_fcwT[k * INDIM + tid];
        #pragma unroll
        for (int b = 0; b < 4; b++) acc[b] = fmaf(wv, xcs[b][k], acc[b]);
    }
    #pragma unroll
    for (int b = 0; b < 4; b++)
        out[(b0 + b) * INDIM + tid] = acc[b];
}

// ---------------------------------------------------------------------------
extern "C" void kernel_launch(void* const* d_in, const int* in_sizes, int n_in,
                              void* d_out, int out_size) {
    const float* x      = (const float*)d_in[0];
    // d_in[1] = w (previous attention weights) unused by reference math
    const float* h_att  = (const float*)d_in[2];
    const float* h_dec  = (const float*)d_in[3];
    const float* enc    = (const float*)d_in[4];
    const float* pre_w1 = (const float*)d_in[5];
    const float* pre_b1 = (const float*)d_in[6];
    const float* pre_w2 = (const float*)d_in[7];
    const float* pre_b2 = (const float*)d_in[8];
    const float* awih   = (const float*)d_in[9];
    const float* awhh   = (const float*)d_in[10];
    const float* abih   = (const float*)d_in[11];
    const float* abhh   = (const float*)d_in[12];
    const float* attW   = (const float*)d_in[13];
    const float* ctxW   = (const float*)d_in[14];
    const float* dwih   = (const float*)d_in[15];
    const float* dwhh   = (const float*)d_in[16];
    const float* dbih   = (const float*)d_in[17];
    const float* dbhh   = (const float*)d_in[18];
    const float* fcw    = (const float*)d_in[19];
    const float* fcb    = (const float*)d_in[20];

    float* out    = (float*)d_out;
    float* w_new  = out + BB * RFRD * MELD;      // +81920
    float* hatt_o = w_new + BB * TT;             // +262144
    float* hdec_o = hatt_o + BB * AA;            // +65536

    float* xc  = nullptr;  cudaGetSymbolAddress((void**)&xc,  g_xc);
    float* xc2 = nullptr;  cudaGetSymbolAddress((void**)&xc2, g_xc2);

    k_transpose_all<<<940, dim3(32, 8)>>>(pre_w1, pre_w2, awih, awhh, dwih, dwhh, fcw);
    k_prenet<<<BB / 4, 128>>>(x, h_att, pre_b1, pre_b2, abih, abhh, hatt_o);
    k_q<<<dim3(BB / 8, 4), 128>>>(hatt_o, attW);
    k_attn_fused<<<BB, 512>>>(enc, ctxW, w_new);
    // decoder layer 0
    k_dec_gemm<<<dim3(BB / 8, 12), 128>>>(xc, h_dec, dbih, dbhh, 0);
    k_dec_gates<<<BB, 256>>>(xc, h_dec, hdec_o, xc2, 0);
    // decoder layer 1
    k_dec_gemm<<<dim3(BB / 8, 12), 128>>>(xc2, h_dec, dbih, dbhh, 1);
    k_dec_gates<<<BB, 256>>>(xc2, h_dec, hdec_o + BB * RR, xc, 1);
    k_fc<<<BB / 4, 160>>>(xc, fcb, out);
}

// round 15
// speedup vs baseline: 1.7382x; 1.0424x over previous
#include <cuda_runtime.h>
#include <math.h>

#define BB   512   // batch
#define TT   512   // encoder time
#define EE   512   // dim_enc
#define AA   128   // dim_att
#define RR   256   // dim_rnn
#define MELD 80
#define RFRD 2
#define INDIM 160  // RFR*MEL

// Scratch (no cudaMalloc allowed)
__device__ float g_q[BB * EE];
__device__ float g_xc[BB * RR];
__device__ float g_xc2[BB * RR];
__device__ float g_g[BB * 6 * RR];         // GRU pre-activations [512][1536]
// Transposed weights (k-major) for coalesced access
__device__ float g_w1T[INDIM * AA];        // [160][128]
__device__ float g_w2T[AA * AA];           // [128][128]
__device__ float g_awihT[AA * 3 * AA];     // [128][384]
__device__ float g_awhhT[AA * 3 * AA];     // [128][384]
__device__ float g_dwihT[2 * RR * 3 * RR]; // [2][256][768]
__device__ float g_dwhhT[2 * RR * 3 * RR]; // [2][256][768]
__device__ float g_fcwT[RR * INDIM];       // [256][160]

__device__ __forceinline__ float sigf(float x) { return 1.f / (1.f + __expf(-x)); }

// ---------------------------------------------------------------------------
// Kernel 0: batched 32x32-tile transpose of all row-major weight matrices.
// ---------------------------------------------------------------------------
__global__ void k_transpose_all(const float* __restrict__ w1, const float* __restrict__ w2,
                                const float* __restrict__ awih, const float* __restrict__ awhh,
                                const float* __restrict__ dwih, const float* __restrict__ dwhh,
                                const float* __restrict__ fcw) {
    __shared__ float s[32][33];
    int t = blockIdx.x;
    const float* src; float* dst; int rows, cols;
    if (t < 20)       {          src = w1;              dst = g_w1T;              rows = 128; cols = 160; }
    else if (t < 36)  { t -= 20; src = w2;              dst = g_w2T;              rows = 128; cols = 128; }
    else if (t < 84)  { t -= 36; src = awih;            dst = g_awihT;            rows = 384; cols = 128; }
    else if (t < 132) { t -= 84; src = awhh;            dst = g_awhhT;            rows = 384; cols = 128; }
    else if (t < 324) { t -= 132; src = dwih;           dst = g_dwihT;            rows = 768; cols = 256; }
    else if (t < 516) { t -= 324; src = dwhh;           dst = g_dwhhT;            rows = 768; cols = 256; }
    else if (t < 708) { t -= 516; src = dwih + 768*256; dst = g_dwihT + 256*768;  rows = 768; cols = 256; }
    else if (t < 900) { t -= 708; src = dwhh + 768*256; dst = g_dwhhT + 256*768;  rows = 768; cols = 256; }
    else              { t -= 900; src = fcw;            dst = g_fcwT;             rows = 160; cols = 256; }
    int tiles_c = cols >> 5;
    int tr = (t / tiles_c) << 5, tc = (t % tiles_c) << 5;
    int tx = threadIdx.x, ty = threadIdx.y;
    #pragma unroll
    for (int yy = 0; yy < 32; yy += 8)
        s[ty + yy][tx] = src[(size_t)(tr + ty + yy) * cols + tc + tx];
    __syncthreads();
    #pragma unroll
    for (int yy = 0; yy < 32; yy += 8)
        dst[(size_t)(tc + ty + yy) * rows + tr + tx] = s[tx][ty + yy];
}

// ---------------------------------------------------------------------------
// Kernel 1: PreNet (2x Linear+ReLU) + attention GRUCell.
// 4 batch rows / block, 128 threads, grid 128.
// ---------------------------------------------------------------------------
__global__ __launch_bounds__(128) void k_prenet(const float* __restrict__ x, const float* __restrict__ h_att,
                         const float* __restrict__ b1, const float* __restrict__ b2,
                         const float* __restrict__ bih, const float* __restrict__ bhh,
                         float* __restrict__ hatt_out) {
    __shared__ float xs[4][INDIM];
    __shared__ float hs[4][AA];
    __shared__ float p1s[4][AA];
    __shared__ float p2s[4][AA];
    int b0 = blockIdx.x * 4, tid = threadIdx.x, j = tid;

    for (int i = tid; i < 4 * INDIM; i += 128)
        xs[i / INDIM][i % INDIM] = x[(b0 + i / INDIM) * INDIM + i % INDIM];
    for (int i = tid; i < 4 * AA; i += 128)
        hs[i >> 7][i & 127] = h_att[(b0 + (i >> 7)) * AA + (i & 127)];
    __syncthreads();

    float acc[4];
    #pragma unroll
    for (int b = 0; b < 4; b++) acc[b] = b1[j];
    #pragma unroll 8
    for (int k = 0; k < INDIM; k++) {
        float wv = g_w1T[k * AA + j];
        #pragma unroll
        for (int b = 0; b < 4; b++) acc[b] = fmaf(wv, xs[b][k], acc[b]);
    }
    #pragma unroll
    for (int b = 0; b < 4; b++) p1s[b][j] = fmaxf(acc[b], 0.f);
    __syncthreads();

    #pragma unroll
    for (int b = 0; b < 4; b++) acc[b] = b2[j];
    #pragma unroll 8
    for (int k = 0; k < AA; k++) {
        float wv = g_w2T[k * AA + j];
        #pragma unroll
        for (int b = 0; b < 4; b++) acc[b] = fmaf(wv, p1s[b][k], acc[b]);
    }
    #pragma unroll
    for (int b = 0; b < 4; b++) p2s[b][j] = fmaxf(acc[b], 0.f);
    __syncthreads();

    float air[4], aiz[4], ain[4], ahr[4], ahz[4], ahn[4];
    float bir = bih[j], biz = bih[AA + j], binn = bih[2 * AA + j];
    float bhr = bhh[j], bhz = bhh[AA + j], bhnn = bhh[2 * AA + j];
    #pragma unroll
    for (int b = 0; b < 4; b++) {
        air[b] = bir; aiz[b] = biz; ain[b] = binn;
        ahr[b] = bhr; ahz[b] = bhz; ahn[b] = bhnn;
    }
    #pragma unroll 4
    for (int k = 0; k < AA; k++) {
        const float* wr = g_awihT + k * (3 * AA);
        const float* ur = g_awhhT + k * (3 * AA);
        float wir = wr[j], wiz = wr[AA + j], win = wr[2 * AA + j];
        float whr = ur[j], whz = ur[AA + j], whn = ur[2 * AA + j];
        #pragma unroll
        for (int b = 0; b < 4; b++) {
            float pv = p2s[b][k], hv = hs[b][k];
            air[b] = fmaf(wir, pv, air[b]);
            aiz[b] = fmaf(wiz, pv, aiz[b]);
            ain[b] = fmaf(win, pv, ain[b]);
            ahr[b] = fmaf(whr, hv, ahr[b]);
            ahz[b] = fmaf(whz, hv, ahz[b]);
            ahn[b] = fmaf(whn, hv, ahn[b]);
        }
    }
    #pragma unroll
    for (int b = 0; b < 4; b++) {
        float r = sigf(air[b] + ahr[b]);
        float z = sigf(aiz[b] + ahz[b]);
        float n = tanhf(ain[b] + r * ahn[b]);
        float hn = (1.f - z) * n + z * hs[b][j];
        hatt_out[(b0 + b) * AA + j] = hn;
        g_xc[(b0 + b) * RR + j] = hn;
    }
}

// ---------------------------------------------------------------------------
// Kernel 1b: q = h_new @ att_W  (512x128 @ 128x512). grid (64,4), 8 batch rows
// and 128 q-columns per block.
// ---------------------------------------------------------------------------
__global__ __launch_bounds__(128) void k_q(const float* __restrict__ h, const float* __restrict__ attW) {
    __shared__ float hs[8][AA];
    int b0 = blockIdx.x * 8, tid = threadIdx.x;
    int col = blockIdx.y * 128 + tid;
    for (int i = tid; i < 8 * AA; i += 128)
        hs[i >> 7][i & 127] = h[(b0 + (i >> 7)) * AA + (i & 127)];
    __syncthreads();
    float acc[8];
    #pragma unroll
    for (int b = 0; b < 8; b++) acc[b] = 0.f;
    #pragma unroll 8
    for (int k = 0; k < AA; k++) {
        float wv = attW[k * EE + col];
        #pragma unroll
        for (int b = 0; b < 8; b++) acc[b] = fmaf(wv, hs[b][k], acc[b]);
    }
    #pragma unroll
    for (int b = 0; b < 8; b++)
        g_q[(b0 + b) * EE + col] = acc[b];
}

// ---------------------------------------------------------------------------
// Kernel 2: fused attention + context projection. One block (512 thr) per
// batch row; two-buffer unroll-2 streaming pipeline.
// ---------------------------------------------------------------------------
#define LOADROW(D0, D1, D2, D3, TI) do { \
    const float4* _rr = rp + (size_t)(TI) * (EE / 4) + lane; \
    D0 = _rr[0]; D1 = _rr[32]; D2 = _rr[64]; D3 = _rr[96]; } while (0)

#define PROC(U0, U1, U2, U3, TI) do { \
    float d = U0.x * q0.x; \
    d = fmaf(U0.y, q0.y, d); d = fmaf(U0.z, q0.z, d); d = fmaf(U0.w, q0.w, d); \
    d = fmaf(U1.x, q1.x, d); d = fmaf(U1.y, q1.y, d); d = fmaf(U1.z, q1.z, d); d = fmaf(U1.w, q1.w, d); \
    d = fmaf(U2.x, q2.x, d); d = fmaf(U2.y, q2.y, d); d = fmaf(U2.z, q2.z, d); d = fmaf(U2.w, q2.w, d); \
    d = fmaf(U3.x, q3.x, d); d = fmaf(U3.y, q3.y, d); d = fmaf(U3.z, q3.z, d); d = fmaf(U3.w, q3.w, d); \
    _Pragma("unroll") \
    for (int _o = 16; _o; _o >>= 1) d += __shfl_xor_sync(0xffffffffu, d, _o); \
    if (lane == 0) sc[TI] = d; \
    float mn = fmaxf(m, d); \
    float p  = __expf(d - mn); \
    if (d > m) { \
        float cc = __expf(m - mn); \
        l *= cc; \
        a0.x *= cc; a0.y *= cc; a0.z *= cc; a0.w *= cc; \
        a1.x *= cc; a1.y *= cc; a1.z *= cc; a1.w *= cc; \
        a2.x *= cc; a2.y *= cc; a2.z *= cc; a2.w *= cc; \
        a3.x *= cc; a3.y *= cc; a3.z *= cc; a3.w *= cc; \
    } \
    l += p; \
    a0.x = fmaf(p, U0.x, a0.x); a0.y = fmaf(p, U0.y, a0.y); \
    a0.z = fmaf(p, U0.z, a0.z); a0.w = fmaf(p, U0.w, a0.w); \
    a1.x = fmaf(p, U1.x, a1.x); a1.y = fmaf(p, U1.y, a1.y); \
    a1.z = fmaf(p, U1.z, a1.z); a1.w = fmaf(p, U1.w, a1.w); \
    a2.x = fmaf(p, U2.x, a2.x); a2.y = fmaf(p, U2.y, a2.y); \
    a2.z = fmaf(p, U2.z, a2.z); a2.w = fmaf(p, U2.w, a2.w); \
    a3.x = fmaf(p, U3.x, a3.x); a3.y = fmaf(p, U3.y, a3.y); \
    a3.z = fmaf(p, U3.z, a3.z); a3.w = fmaf(p, U3.w, a3.w); \
    m = mn; } while (0)

__global__ __launch_bounds__(512) void k_attn_fused(const float* __restrict__ enc,
                                                    const float* __restrict__ ctxW,
                                                    float* __restrict__ w_out) {
    __shared__ float sc[TT];
    __shared__ float ctx_s[EE];
    __shared__ float wm[16], wl[16];
    __shared__ float part[4][AA];
    int b = blockIdx.x, tid = threadIdx.x, lane = tid & 31, warp = tid >> 5;

    ctx_s[tid] = 0.f;

    const float4* q4p = (const float4*)(g_q + (size_t)b * EE);
    float4 q0 = q4p[lane], q1 = q4p[lane + 32], q2 = q4p[lane + 64], q3 = q4p[lane + 96];
    __syncthreads();

    const float4* rp = (const float4*)(enc + (size_t)b * TT * EE);
    const int t0 = warp * 32;

    float m = -INFINITY, l = 0.f;
    float4 a0 = {0,0,0,0}, a1 = {0,0,0,0}, a2 = {0,0,0,0}, a3 = {0,0,0,0};

    float4 A0, A1, A2, A3, B0, B1, B2, B3;
    LOADROW(A0, A1, A2, A3, t0);
    LOADROW(B0, B1, B2, B3, t0 + 1);

    #pragma unroll 4
    for (int i = 0; i < 32; i += 2) {
        PROC(A0, A1, A2, A3, t0 + i);
        if (i + 2 < 32) LOADROW(A0, A1, A2, A3, t0 + i + 2);
        PROC(B0, B1, B2, B3, t0 + i + 1);
        if (i + 3 < 32) LOADROW(B0, B1, B2, B3, t0 + i + 3);
    }

    if (lane == 0) { wm[warp] = m; wl[warp] = l; }
    __syncthreads();

    float gm = wm[0];
    #pragma unroll
    for (int w = 1; w < 16; w++) gm = fmaxf(gm, wm[w]);
    float gl = 0.f;
    #pragma unroll
    for (int w = 0; w < 16; w++) gl += wl[w] * __expf(wm[w] - gm);

    float f = __expf(m - gm);
    int e0 = lane * 4;
    atomicAdd(&ctx_s[e0 + 0],   a0.x * f); atomicAdd(&ctx_s[e0 + 1],   a0.y * f);
    atomicAdd(&ctx_s[e0 + 2],   a0.z * f); atomicAdd(&ctx_s[e0 + 3],   a0.w * f);
    atomicAdd(&ctx_s[e0 + 128], a1.x * f); atomicAdd(&ctx_s[e0 + 129], a1.y * f);
    atomicAdd(&ctx_s[e0 + 130], a1.z * f); atomicAdd(&ctx_s[e0 + 131], a1.w * f);
    atomicAdd(&ctx_s[e0 + 256], a2.x * f); atomicAdd(&ctx_s[e0 + 257], a2.y * f);
    atomicAdd(&ctx_s[e0 + 258], a2.z * f); atomicAdd(&ctx_s[e0 + 259], a2.w * f);
    atomicAdd(&ctx_s[e0 + 384], a3.x * f); atomicAdd(&ctx_s[e0 + 385], a3.y * f);
    atomicAdd(&ctx_s[e0 + 386], a3.z * f); atomicAdd(&ctx_s[e0 + 387], a3.w * f);
    __syncthreads();

    float invl = 1.f / gl;
    w_out[(size_t)b * TT + tid] = __expf(sc[tid] - gm) * invl;

    int jj = tid & 127, chunk = tid >> 7;
    float a = 0.f;
    #pragma unroll 8
    for (int e = chunk * 128; e < chunk * 128 + 128; e++)
        a = fmaf(ctx_s[e], ctxW[e * AA + jj], a);
    part[chunk][jj] = a;
    __syncthreads();
    if (tid < 128)
        g_xc[(size_t)b * RR + 128 + tid] =
            (part[0][tid] + part[1][tid] + part[2][tid] + part[3][tid]) * invl;
}

// ---------------------------------------------------------------------------
// Kernel 3a: GRU pre-activation GEMM, G[512][1536] = act @ W^T + bias.
// grid (64, 12): 8 batch rows x 128 of 1536 output cols. Cols [0,768) = gi
// (act = xc, W = wihT); cols [768,1536) = gh (act = h, W = whhT).
// ---------------------------------------------------------------------------
__global__ __launch_bounds__(128) void k_dec_gemm(const float* __restrict__ xc_in,
                                                  const float* __restrict__ hdec_in,
                                                  const float* __restrict__ bih_all,
                                                  const float* __restrict__ bhh_all,
                                                  int layer) {
    __shared__ float as[8][RR];
    int b0 = blockIdx.x * 8, tid = threadIdx.x, yt = blockIdx.y;
    int c = (yt % 6) * 128 + tid;           // col within [0,768)
    bool is_ih = (yt < 6);
    const float* act  = is_ih ? xc_in : (hdec_in + (size_t)layer * BB * RR);
    const float* W    = (is_ih ? g_dwihT : g_dwhhT) + (size_t)layer * RR * 3 * RR;
    const float* bias = (is_ih ? bih_all : bhh_all) + layer * 3 * RR;

    for (int i = tid; i < 8 * RR; i += 128) {
        int b = i >> 8, kk = i & 255;
        as[b][kk] = act[(b0 + b) * RR + kk];
    }
    __syncthreads();

    float acc[8];
    float bv = bias[c];
    #pragma unroll
    for (int b = 0; b < 8; b++) acc[b] = bv;

    #pragma unroll 2
    for (int k = 0; k < RR; k += 4) {
        float w0 = W[(size_t)(k + 0) * 768 + c];
        float w1 = W[(size_t)(k + 1) * 768 + c];
        float w2 = W[(size_t)(k + 2) * 768 + c];
        float w3 = W[(size_t)(k + 3) * 768 + c];
        #pragma unroll
        for (int b = 0; b < 8; b++) {
            float4 av = *(const float4*)&as[b][k];
            acc[b] = fmaf(w0, av.x, acc[b]);
            acc[b] = fmaf(w1, av.y, acc[b]);
            acc[b] = fmaf(w2, av.z, acc[b]);
            acc[b] = fmaf(w3, av.w, acc[b]);
        }
    }
    #pragma unroll
    for (int b = 0; b < 8; b++)
        g_g[(size_t)(b0 + b) * 1536 + yt * 128 + tid] = acc[b];
}

// ---------------------------------------------------------------------------
// Kernel 3b: GRU gate elementwise. grid 512, block 256.
// ---------------------------------------------------------------------------
__global__ __launch_bounds__(256) void k_dec_gates(const float* __restrict__ xc_in,
                                                   const float* __restrict__ hdec_in,
                                                   float* __restrict__ hdec_out,
                                                   float* __restrict__ xc_out, int layer) {
    int b = blockIdx.x, j = threadIdx.x;
    const float* Gb = g_g + (size_t)b * 1536;
    float gr = Gb[j],        gz = Gb[256 + j],  gn = Gb[512 + j];
    float hr = Gb[768 + j],  hz = Gb[1024 + j], hnv = Gb[1280 + j];
    float h  = hdec_in[(size_t)layer * BB * RR + b * RR + j];
    float xc = xc_in[b * RR + j];
    float r = sigf(gr + hr);
    float z = sigf(gz + hz);
    float n = tanhf(gn + r * hnv);
    float hn = (1.f - z) * n + z * h;
    hdec_out[b * RR + j] = hn;
    xc_out[b * RR + j]   = xc + hn;
}

// ---------------------------------------------------------------------------
// Kernel 4: out = xc @ fc_w^T + fc_b. 4 batch rows/block, grid 128.
// ---------------------------------------------------------------------------
__global__ __launch_bounds__(160) void k_fc(const float* __restrict__ xc_in,
                     const float* __restrict__ fcb,
                     float* __restrict__ out) {
    __shared__ float xcs[4][RR];
    int b0 = blockIdx.x * 4, tid = threadIdx.x;
    for (int i = tid; i < 4 * RR; i += 160) {
        int b = i >> 8, kk = i & 255;
        xcs[b][kk] = xc_in[(b0 + b) * RR + kk];
    }
    __syncthreads();
    float acc[4];
    float bb = fcb[tid];
    #pragma unroll
    for (int b = 0; b < 4; b++) acc[b] = bb;
    #pragma unroll 8
    for (int k = 0; k < RR; k++) {
        float wv = g_fcwT[k * INDIM + tid];
        #pragma unroll
        for (int b = 0; b < 4; b++) acc[b] = fmaf(wv, xcs[b][k], acc[b]);
    }
    #pragma unroll
    for (int b = 0; b < 4; b++)
        out[(b0 + b) * INDIM + tid] = acc[b];
}

// ---------------------------------------------------------------------------
extern "C" void kernel_launch(void* const* d_in, const int* in_sizes, int n_in,
                              void* d_out, int out_size) {
    const float* x      = (const float*)d_in[0];
    // d_in[1] = w (previous attention weights) unused by reference math
    const float* h_att  = (const float*)d_in[2];
    const float* h_dec  = (const float*)d_in[3];
    const float* enc    = (const float*)d_in[4];
    const float* pre_w1 = (const float*)d_in[5];
    const float* pre_b1 = (const float*)d_in[6];
    const float* pre_w2 = (const float*)d_in[7];
    const float* pre_b2 = (const float*)d_in[8];
    const float* awih   = (const float*)d_in[9];
    const float* awhh   = (const float*)d_in[10];
    const float* abih   = (const float*)d_in[11];
    const float* abhh   = (const float*)d_in[12];
    const float* attW   = (const float*)d_in[13];
    const float* ctxW   = (const float*)d_in[14];
    const float* dwih   = (const float*)d_in[15];
    const float* dwhh   = (const float*)d_in[16];
    const float* dbih   = (const float*)d_in[17];
    const float* dbhh   = (const float*)d_in[18];
    const float* fcw    = (const float*)d_in[19];
    const float* fcb    = (const float*)d_in[20];

    float* out    = (float*)d_out;
    float* w_new  = out + BB * RFRD * MELD;      // +81920
    float* hatt_o = w_new + BB * TT;             // +262144
    float* hdec_o = hatt_o + BB * AA;            // +65536

    float* xc  = nullptr;  cudaGetSymbolAddress((void**)&xc,  g_xc);
    float* xc2 = nullptr;  cudaGetSymbolAddress((void**)&xc2, g_xc2);

    k_transpose_all<<<940, dim3(32, 8)>>>(pre_w1, pre_w2, awih, awhh, dwih, dwhh, fcw);
    k_prenet<<<BB / 4, 128>>>(x, h_att, pre_b1, pre_b2, abih, abhh, hatt_o);
    k_q<<<dim3(BB / 8, 4), 128>>>(hatt_o, attW);
    k_attn_fused<<<BB, 512>>>(enc, ctxW, w_new);
    // decoder layer 0
    k_dec_gemm<<<dim3(BB / 8, 12), 128>>>(xc, h_dec, dbih, dbhh, 0);
    k_dec_gates<<<BB, 256>>>(xc, h_dec, hdec_o, xc2, 0);
    // decoder layer 1
    k_dec_gemm<<<dim3(BB / 8, 12), 128>>>(xc2, h_dec, dbih, dbhh, 1);
    k_dec_gates<<<BB, 256>>>(xc2, h_dec, hdec_o + BB * RR, xc, 1);
    k_fc<<<BB / 4, 160>>>(xc, fcb, out);
}

// round 16
// speedup vs baseline: 1.8688x; 1.0752x over previous
#include <cuda_runtime.h>
#include <math.h>

#define BB   512   // batch
#define TT   512   // encoder time
#define EE   512   // dim_enc
#define AA   128   // dim_att
#define RR   256   // dim_rnn
#define MELD 80
#define RFRD 2
#define INDIM 160  // RFR*MEL

// Scratch (no cudaMalloc allowed)
__device__ float g_q[BB * EE];
__device__ float g_xc[BB * RR];
__device__ float g_xc2[BB * RR];
__device__ float g_g[BB * 6 * RR];         // GRU pre-activations [512][1536]
// Transposed weights (k-major) for coalesced access
__device__ float g_w1T[INDIM * AA];        // [160][128]
__device__ float g_w2T[AA * AA];           // [128][128]
__device__ float g_awihT[AA * 3 * AA];     // [128][384]
__device__ float g_awhhT[AA * 3 * AA];     // [128][384]
__device__ float g_dwihT[2 * RR * 3 * RR]; // [2][256][768]
__device__ float g_dwhhT[2 * RR * 3 * RR]; // [2][256][768]
__device__ float g_fcwT[RR * INDIM];       // [256][160]

__device__ __forceinline__ float sigf(float x) { return 1.f / (1.f + __expf(-x)); }

// ---------------------------------------------------------------------------
// Kernel 0: batched 32x32-tile transpose of all row-major weight matrices.
// ---------------------------------------------------------------------------
__global__ void k_transpose_all(const float* __restrict__ w1, const float* __restrict__ w2,
                                const float* __restrict__ awih, const float* __restrict__ awhh,
                                const float* __restrict__ dwih, const float* __restrict__ dwhh,
                                const float* __restrict__ fcw) {
    __shared__ float s[32][33];
    int t = blockIdx.x;
    const float* src; float* dst; int rows, cols;
    if (t < 20)       {          src = w1;              dst = g_w1T;              rows = 128; cols = 160; }
    else if (t < 36)  { t -= 20; src = w2;              dst = g_w2T;              rows = 128; cols = 128; }
    else if (t < 84)  { t -= 36; src = awih;            dst = g_awihT;            rows = 384; cols = 128; }
    else if (t < 132) { t -= 84; src = awhh;            dst = g_awhhT;            rows = 384; cols = 128; }
    else if (t < 324) { t -= 132; src = dwih;           dst = g_dwihT;            rows = 768; cols = 256; }
    else if (t < 516) { t -= 324; src = dwhh;           dst = g_dwhhT;            rows = 768; cols = 256; }
    else if (t < 708) { t -= 516; src = dwih + 768*256; dst = g_dwihT + 256*768;  rows = 768; cols = 256; }
    else if (t < 900) { t -= 708; src = dwhh + 768*256; dst = g_dwhhT + 256*768;  rows = 768; cols = 256; }
    else              { t -= 900; src = fcw;            dst = g_fcwT;             rows = 160; cols = 256; }
    int tiles_c = cols >> 5;
    int tr = (t / tiles_c) << 5, tc = (t % tiles_c) << 5;
    int tx = threadIdx.x, ty = threadIdx.y;
    #pragma unroll
    for (int yy = 0; yy < 32; yy += 8)
        s[ty + yy][tx] = src[(size_t)(tr + ty + yy) * cols + tc + tx];
    __syncthreads();
    #pragma unroll
    for (int yy = 0; yy < 32; yy += 8)
        dst[(size_t)(tc + ty + yy) * rows + tr + tx] = s[tx][ty + yy];
}

// ---------------------------------------------------------------------------
// Kernel 1: PreNet (2x Linear+ReLU) + attention GRUCell + q GEMM (fused).
// 4 batch rows / block, 128 threads, grid 128.
// ---------------------------------------------------------------------------
__global__ __launch_bounds__(128) void k_prenet(const float* __restrict__ x, const float* __restrict__ h_att,
                         const float* __restrict__ b1, const float* __restrict__ b2,
                         const float* __restrict__ bih, const float* __restrict__ bhh,
                         const float* __restrict__ attW,
                         float* __restrict__ hatt_out) {
    __shared__ float xs[4][INDIM];
    __shared__ float hs[4][AA];
    __shared__ float p1s[4][AA];
    __shared__ float p2s[4][AA];
    int b0 = blockIdx.x * 4, tid = threadIdx.x, j = tid;

    for (int i = tid; i < 4 * INDIM; i += 128)
        xs[i / INDIM][i % INDIM] = x[(b0 + i / INDIM) * INDIM + i % INDIM];
    for (int i = tid; i < 4 * AA; i += 128)
        hs[i >> 7][i & 127] = h_att[(b0 + (i >> 7)) * AA + (i & 127)];
    __syncthreads();

    float acc[4];
    #pragma unroll
    for (int b = 0; b < 4; b++) acc[b] = b1[j];
    #pragma unroll 8
    for (int k = 0; k < INDIM; k++) {
        float wv = g_w1T[k * AA + j];
        #pragma unroll
        for (int b = 0; b < 4; b++) acc[b] = fmaf(wv, xs[b][k], acc[b]);
    }
    #pragma unroll
    for (int b = 0; b < 4; b++) p1s[b][j] = fmaxf(acc[b], 0.f);
    __syncthreads();

    #pragma unroll
    for (int b = 0; b < 4; b++) acc[b] = b2[j];
    #pragma unroll 8
    for (int k = 0; k < AA; k++) {
        float wv = g_w2T[k * AA + j];
        #pragma unroll
        for (int b = 0; b < 4; b++) acc[b] = fmaf(wv, p1s[b][k], acc[b]);
    }
    #pragma unroll
    for (int b = 0; b < 4; b++) p2s[b][j] = fmaxf(acc[b], 0.f);
    __syncthreads();

    float air[4], aiz[4], ain[4], ahr[4], ahz[4], ahn[4];
    float bir = bih[j], biz = bih[AA + j], binn = bih[2 * AA + j];
    float bhr = bhh[j], bhz = bhh[AA + j], bhnn = bhh[2 * AA + j];
    #pragma unroll
    for (int b = 0; b < 4; b++) {
        air[b] = bir; aiz[b] = biz; ain[b] = binn;
        ahr[b] = bhr; ahz[b] = bhz; ahn[b] = bhnn;
    }
    #pragma unroll 4
    for (int k = 0; k < AA; k++) {
        const float* wr = g_awihT + k * (3 * AA);
        const float* ur = g_awhhT + k * (3 * AA);
        float wir = wr[j], wiz = wr[AA + j], win = wr[2 * AA + j];
        float whr = ur[j], whz = ur[AA + j], whn = ur[2 * AA + j];
        #pragma unroll
        for (int b = 0; b < 4; b++) {
            float pv = p2s[b][k], hv = hs[b][k];
            air[b] = fmaf(wir, pv, air[b]);
            aiz[b] = fmaf(wiz, pv, aiz[b]);
            ain[b] = fmaf(win, pv, ain[b]);
            ahr[b] = fmaf(whr, hv, ahr[b]);
            ahz[b] = fmaf(whz, hv, ahz[b]);
            ahn[b] = fmaf(whn, hv, ahn[b]);
        }
    }
    __syncthreads();   // p1s reused to stage h_new
    #pragma unroll
    for (int b = 0; b < 4; b++) {
        float r = sigf(air[b] + ahr[b]);
        float z = sigf(aiz[b] + ahz[b]);
        float n = tanhf(ain[b] + r * ahn[b]);
        float hn = (1.f - z) * n + z * hs[b][j];
        hatt_out[(b0 + b) * AA + j] = hn;
        g_xc[(b0 + b) * RR + j] = hn;
        p1s[b][j] = hn;
    }
    __syncthreads();

    // q = h_new @ att_W  (att_W [A, E] row-major; coalesced across tid)
    float q0[4], q1[4], q2[4], q3[4];
    #pragma unroll
    for (int b = 0; b < 4; b++) { q0[b] = 0.f; q1[b] = 0.f; q2[b] = 0.f; q3[b] = 0.f; }
    #pragma unroll 4
    for (int k = 0; k < AA; k++) {
        float wv0 = attW[k * EE + tid];
        float wv1 = attW[k * EE + tid + 128];
        float wv2 = attW[k * EE + tid + 256];
        float wv3 = attW[k * EE + tid + 384];
        #pragma unroll
        for (int b = 0; b < 4; b++) {
            float hv = p1s[b][k];
            q0[b] = fmaf(wv0, hv, q0[b]);
            q1[b] = fmaf(wv1, hv, q1[b]);
            q2[b] = fmaf(wv2, hv, q2[b]);
            q3[b] = fmaf(wv3, hv, q3[b]);
        }
    }
    #pragma unroll
    for (int b = 0; b < 4; b++) {
        g_q[(b0 + b) * EE + tid]       = q0[b];
        g_q[(b0 + b) * EE + tid + 128] = q1[b];
        g_q[(b0 + b) * EE + tid + 256] = q2[b];
        g_q[(b0 + b) * EE + tid + 384] = q3[b];
    }
}

// ---------------------------------------------------------------------------
// Kernel 2: fused attention + context projection. One block (512 thr) per
// batch row; depth-3 register streaming pipeline (3 rows / 6KB in flight per
// warp) to cover loaded-DRAM latency.
// ---------------------------------------------------------------------------
#define LOADROW(D0, D1, D2, D3, TI) do { \
    const float4* _rr = rp + (size_t)(TI) * (EE / 4) + lane; \
    D0 = _rr[0]; D1 = _rr[32]; D2 = _rr[64]; D3 = _rr[96]; } while (0)

#define PROC(U0, U1, U2, U3, TI) do { \
    float d = U0.x * q0.x; \
    d = fmaf(U0.y, q0.y, d); d = fmaf(U0.z, q0.z, d); d = fmaf(U0.w, q0.w, d); \
    d = fmaf(U1.x, q1.x, d); d = fmaf(U1.y, q1.y, d); d = fmaf(U1.z, q1.z, d); d = fmaf(U1.w, q1.w, d); \
    d = fmaf(U2.x, q2.x, d); d = fmaf(U2.y, q2.y, d); d = fmaf(U2.z, q2.z, d); d = fmaf(U2.w, q2.w, d); \
    d = fmaf(U3.x, q3.x, d); d = fmaf(U3.y, q3.y, d); d = fmaf(U3.z, q3.z, d); d = fmaf(U3.w, q3.w, d); \
    _Pragma("unroll") \
    for (int _o = 16; _o; _o >>= 1) d += __shfl_xor_sync(0xffffffffu, d, _o); \
    if (lane == 0) sc[TI] = d; \
    float mn = fmaxf(m, d); \
    float p  = __expf(d - mn); \
    if (d > m) { \
        float cc = __expf(m - mn); \
        l *= cc; \
        a0.x *= cc; a0.y *= cc; a0.z *= cc; a0.w *= cc; \
        a1.x *= cc; a1.y *= cc; a1.z *= cc; a1.w *= cc; \
        a2.x *= cc; a2.y *= cc; a2.z *= cc; a2.w *= cc; \
        a3.x *= cc; a3.y *= cc; a3.z *= cc; a3.w *= cc; \
    } \
    l += p; \
    a0.x = fmaf(p, U0.x, a0.x); a0.y = fmaf(p, U0.y, a0.y); \
    a0.z = fmaf(p, U0.z, a0.z); a0.w = fmaf(p, U0.w, a0.w); \
    a1.x = fmaf(p, U1.x, a1.x); a1.y = fmaf(p, U1.y, a1.y); \
    a1.z = fmaf(p, U1.z, a1.z); a1.w = fmaf(p, U1.w, a1.w); \
    a2.x = fmaf(p, U2.x, a2.x); a2.y = fmaf(p, U2.y, a2.y); \
    a2.z = fmaf(p, U2.z, a2.z); a2.w = fmaf(p, U2.w, a2.w); \
    a3.x = fmaf(p, U3.x, a3.x); a3.y = fmaf(p, U3.y, a3.y); \
    a3.z = fmaf(p, U3.z, a3.z); a3.w = fmaf(p, U3.w, a3.w); \
    m = mn; } while (0)

__global__ __launch_bounds__(512) void k_attn_fused(const float* __restrict__ enc,
                                                    const float* __restrict__ ctxW,
                                                    float* __restrict__ w_out) {
    __shared__ float sc[TT];
    __shared__ float ctx_s[EE];
    __shared__ float wm[16], wl[16];
    __shared__ float part[4][AA];
    int b = blockIdx.x, tid = threadIdx.x, lane = tid & 31, warp = tid >> 5;

    ctx_s[tid] = 0.f;

    const float4* q4p = (const float4*)(g_q + (size_t)b * EE);
    float4 q0 = q4p[lane], q1 = q4p[lane + 32], q2 = q4p[lane + 64], q3 = q4p[lane + 96];
    __syncthreads();

    const float4* rp = (const float4*)(enc + (size_t)b * TT * EE);
    const int t0 = warp * 32;

    float m = -INFINITY, l = 0.f;
    float4 a0 = {0,0,0,0}, a1 = {0,0,0,0}, a2 = {0,0,0,0}, a3 = {0,0,0,0};

    float4 A0, A1, A2, A3, B0, B1, B2, B3, C0, C1, C2, C3;
    LOADROW(A0, A1, A2, A3, t0);
    LOADROW(B0, B1, B2, B3, t0 + 1);
    LOADROW(C0, C1, C2, C3, t0 + 2);

    #pragma unroll 2
    for (int i = 0; i < 30; i += 3) {
        PROC(A0, A1, A2, A3, t0 + i);
        LOADROW(A0, A1, A2, A3, t0 + i + 3);
        PROC(B0, B1, B2, B3, t0 + i + 1);
        if (i + 4 < 32) LOADROW(B0, B1, B2, B3, t0 + i + 4);
        PROC(C0, C1, C2, C3, t0 + i + 2);
        if (i + 5 < 32) LOADROW(C0, C1, C2, C3, t0 + i + 5);
    }
    PROC(A0, A1, A2, A3, t0 + 30);
    PROC(B0, B1, B2, B3, t0 + 31);

    if (lane == 0) { wm[warp] = m; wl[warp] = l; }
    __syncthreads();

    float gm = wm[0];
    #pragma unroll
    for (int w = 1; w < 16; w++) gm = fmaxf(gm, wm[w]);
    float gl = 0.f;
    #pragma unroll
    for (int w = 0; w < 16; w++) gl += wl[w] * __expf(wm[w] - gm);

    float f = __expf(m - gm);
    int e0 = lane * 4;
    atomicAdd(&ctx_s[e0 + 0],   a0.x * f); atomicAdd(&ctx_s[e0 + 1],   a0.y * f);
    atomicAdd(&ctx_s[e0 + 2],   a0.z * f); atomicAdd(&ctx_s[e0 + 3],   a0.w * f);
    atomicAdd(&ctx_s[e0 + 128], a1.x * f); atomicAdd(&ctx_s[e0 + 129], a1.y * f);
    atomicAdd(&ctx_s[e0 + 130], a1.z * f); atomicAdd(&ctx_s[e0 + 131], a1.w * f);
    atomicAdd(&ctx_s[e0 + 256], a2.x * f); atomicAdd(&ctx_s[e0 + 257], a2.y * f);
    atomicAdd(&ctx_s[e0 + 258], a2.z * f); atomicAdd(&ctx_s[e0 + 259], a2.w * f);
    atomicAdd(&ctx_s[e0 + 384], a3.x * f); atomicAdd(&ctx_s[e0 + 385], a3.y * f);
    atomicAdd(&ctx_s[e0 + 386], a3.z * f); atomicAdd(&ctx_s[e0 + 387], a3.w * f);
    __syncthreads();

    float invl = 1.f / gl;
    w_out[(size_t)b * TT + tid] = __expf(sc[tid] - gm) * invl;

    int jj = tid & 127, chunk = tid >> 7;
    float a = 0.f;
    #pragma unroll 8
    for (int e = chunk * 128; e < chunk * 128 + 128; e++)
        a = fmaf(ctx_s[e], ctxW[e * AA + jj], a);
    part[chunk][jj] = a;
    __syncthreads();
    if (tid < 128)
        g_xc[(size_t)b * RR + 128 + tid] =
            (part[0][tid] + part[1][tid] + part[2][tid] + part[3][tid]) * invl;
}

// ---------------------------------------------------------------------------
// Kernel 3a: GRU pre-activation GEMM, G[512][1536] = act @ W^T + bias.
// grid (64, 12): 8 batch rows x 128 output cols per block.
// ---------------------------------------------------------------------------
__global__ __launch_bounds__(128) void k_dec_gemm(const float* __restrict__ xc_in,
                                                  const float* __restrict__ hdec_in,
                                                  const float* __restrict__ bih_all,
                                                  const float* __restrict__ bhh_all,
                                                  int layer) {
    __shared__ float as[8][RR];
    int b0 = blockIdx.x * 8, tid = threadIdx.x, yt = blockIdx.y;
    int c = (yt % 6) * 128 + tid;
    bool is_ih = (yt < 6);
    const float* act  = is_ih ? xc_in : (hdec_in + (size_t)layer * BB * RR);
    const float* W    = (is_ih ? g_dwihT : g_dwhhT) + (size_t)layer * RR * 3 * RR;
    const float* bias = (is_ih ? bih_all : bhh_all) + layer * 3 * RR;

    for (int i = tid; i < 8 * RR; i += 128) {
        int b = i >> 8, kk = i & 255;
        as[b][kk] = act[(b0 + b) * RR + kk];
    }
    __syncthreads();

    float acc[8];
    float bv = bias[c];
    #pragma unroll
    for (int b = 0; b < 8; b++) acc[b] = bv;

    #pragma unroll 4
    for (int k = 0; k < RR; k += 4) {
        float w0 = W[(size_t)(k + 0) * 768 + c];
        float w1 = W[(size_t)(k + 1) * 768 + c];
        float w2 = W[(size_t)(k + 2) * 768 + c];
        float w3 = W[(size_t)(k + 3) * 768 + c];
        #pragma unroll
        for (int b = 0; b < 8; b++) {
            float4 av = *(const float4*)&as[b][k];
            acc[b] = fmaf(w0, av.x, acc[b]);
            acc[b] = fmaf(w1, av.y, acc[b]);
            acc[b] = fmaf(w2, av.z, acc[b]);
            acc[b] = fmaf(w3, av.w, acc[b]);
        }
    }
    #pragma unroll
    for (int b = 0; b < 8; b++)
        g_g[(size_t)(b0 + b) * 1536 + yt * 128 + tid] = acc[b];
}

// ---------------------------------------------------------------------------
// Kernel 3b: GRU gate elementwise. grid 512, block 256.
// ---------------------------------------------------------------------------
__global__ __launch_bounds__(256) void k_dec_gates(const float* __restrict__ xc_in,
                                                   const float* __restrict__ hdec_in,
                                                   float* __restrict__ hdec_out,
                                                   float* __restrict__ xc_out, int layer) {
    int b = blockIdx.x, j = threadIdx.x;
    const float* Gb = g_g + (size_t)b * 1536;
    float gr = Gb[j],        gz = Gb[256 + j],  gn = Gb[512 + j];
    float hr = Gb[768 + j],  hz = Gb[1024 + j], hnv = Gb[1280 + j];
    float h  = hdec_in[(size_t)layer * BB * RR + b * RR + j];
    float xc = xc_in[b * RR + j];
    float r = sigf(gr + hr);
    float z = sigf(gz + hz);
    float n = tanhf(gn + r * hnv);
    float hn = (1.f - z) * n + z * h;
    hdec_out[b * RR + j] = hn;
    xc_out[b * RR + j]   = xc + hn;
}

// ---------------------------------------------------------------------------
// Kernel 4: out = xc @ fc_w^T + fc_b. 4 batch rows/block, grid 128.
// ---------------------------------------------------------------------------
__global__ __launch_bounds__(160) void k_fc(const float* __restrict__ xc_in,
                     const float* __restrict__ fcb,
                     float* __restrict__ out) {
    __shared__ float xcs[4][RR];
    int b0 = blockIdx.x * 4, tid = threadIdx.x;
    for (int i = tid; i < 4 * RR; i += 160) {
        int b = i >> 8, kk = i & 255;
        xcs[b][kk] = xc_in[(b0 + b) * RR + kk];
    }
    __syncthreads();
    float acc[4];
    float bb = fcb[tid];
    #pragma unroll
    for (int b = 0; b < 4; b++) acc[b] = bb;
    #pragma unroll 8
    for (int k = 0; k < RR; k++) {
        float wv = g_fcwT[k * INDIM + tid];
        #pragma unroll
        for (int b = 0; b < 4; b++) acc[b] = fmaf(wv, xcs[b][k], acc[b]);
    }
    #pragma unroll
    for (int b = 0; b < 4; b++)
        out[(b0 + b) * INDIM + tid] = acc[b];
}

// ---------------------------------------------------------------------------
extern "C" void kernel_launch(void* const* d_in, const int* in_sizes, int n_in,
                              void* d_out, int out_size) {
    const float* x      = (const float*)d_in[0];
    // d_in[1] = w (previous attention weights) unused by reference math
    const float* h_att  = (const float*)d_in[2];
    const float* h_dec  = (const float*)d_in[3];
    const float* enc    = (const float*)d_in[4];
    const float* pre_w1 = (const float*)d_in[5];
    const float* pre_b1 = (const float*)d_in[6];
    const float* pre_w2 = (const float*)d_in[7];
    const float* pre_b2 = (const float*)d_in[8];
    const float* awih   = (const float*)d_in[9];
    const float* awhh   = (const float*)d_in[10];
    const float* abih   = (const float*)d_in[11];
    const float* abhh   = (const float*)d_in[12];
    const float* attW   = (const float*)d_in[13];
    const float* ctxW   = (const float*)d_in[14];
    const float* dwih   = (const float*)d_in[15];
    const float* dwhh   = (const float*)d_in[16];
    const float* dbih   = (const float*)d_in[17];
    const float* dbhh   = (const float*)d_in[18];
    const float* fcw    = (const float*)d_in[19];
    const float* fcb    = (const float*)d_in[20];

    float* out    = (float*)d_out;
    float* w_new  = out + BB * RFRD * MELD;      // +81920
    float* hatt_o = w_new + BB * TT;             // +262144
    float* hdec_o = hatt_o + BB * AA;            // +65536

    float* xc  = nullptr;  cudaGetSymbolAddress((void**)&xc,  g_xc);
    float* xc2 = nullptr;  cudaGetSymbolAddress((void**)&xc2, g_xc2);

    k_transpose_all<<<940, dim3(32, 8)>>>(pre_w1, pre_w2, awih, awhh, dwih, dwhh, fcw);
    k_prenet<<<BB / 4, 128>>>(x, h_att, pre_b1, pre_b2, abih, abhh, attW, hatt_o);
    k_attn_fused<<<BB, 512>>>(enc, ctxW, w_new);
    // decoder layer 0
    k_dec_gemm<<<dim3(BB / 8, 12), 128>>>(xc, h_dec, dbih, dbhh, 0);
    k_dec_gates<<<BB, 256>>>(xc, h_dec, hdec_o, xc2, 0);
    // decoder layer 1
    k_dec_gemm<<<dim3(BB / 8, 12), 128>>>(xc2, h_dec, dbih, dbhh, 1);
    k_dec_gates<<<BB, 256>>>(xc2, h_dec, hdec_o + BB * RR, xc, 1);
    k_fc<<<BB / 4, 160>>>(xc, fcb, out);
}